// round 2
// baseline (speedup 1.0000x reference)
#include <cuda_runtime.h>
#include <cuda_bf16.h>
#include <math.h>

typedef unsigned long long ull;

#define B_  4
#define S_  8192
#define D_  1024
#define H_  16
#define DH_ 64
#define M_  (B_*S_)

// -------- scratch (device globals: sanctioned, no cudaMalloc) --------
__device__ float g_mq[(size_t)M_ * D_];        // mixed_q  [B,S,D]
__device__ float g_mk[(size_t)M_ * D_];        // mixed_k  [B,S,D]
__device__ float g_score[B_ * H_ * S_];        // scores   [B,H,S]
__device__ float g_pq[B_ * D_];                // pooled_q [B,D]
__device__ float g_pk[B_ * D_];                // pooled_k [B,D]

// -------- packed fp32x2 FMA (Blackwell) --------
__device__ __forceinline__ void ffma2(ull& d, ull a, ull b) {
    asm("fma.rn.f32x2 %0, %1, %2, %0;" : "+l"(d) : "l"(a), "l"(b));
}
__device__ __forceinline__ float lo32(ull v) { return __uint_as_float((unsigned)(v & 0xffffffffull)); }
__device__ __forceinline__ float hi32(ull v) { return __uint_as_float((unsigned)(v >> 32)); }

// =====================================================================
// SGEMM: C[M,N] = A[M,K] (* colscale per (batch,k)) @ W[K,N] + bias (+ addC)
// M=32768, N=1024, K=1024. Block tile 128x128, BK=16, 256 threads,
// thread tile 8x8 computed as 4 row-pairs x 8 cols via fma.rn.f32x2.
// =====================================================================
template <bool HAS_SCALE, bool HAS_ADD>
__global__ __launch_bounds__(256, 2)
void sgemm_kernel(const float* __restrict__ A, const float* __restrict__ W,
                  const float* __restrict__ bias, const float* __restrict__ scaleA,
                  const float* __restrict__ addC, float* __restrict__ C)
{
    __shared__ __align__(16) float As[16][132];   // [k][m], padded rows (528B, 16B-divisible)
    __shared__ __align__(16) float Ws2[16][256];  // [k][2n], each W value duplicated

    const int tid  = threadIdx.x;
    const int ty   = tid >> 4;        // 0..15 -> row group
    const int tx   = tid & 15;        // 0..15 -> col group
    const int brow = blockIdx.y * 128;
    const int bcol = blockIdx.x * 128;
    const int batch = brow >> 13;     // S=8192, tiles never straddle batches

    ull acc[4][8];
    #pragma unroll
    for (int i = 0; i < 4; i++)
        #pragma unroll
        for (int j = 0; j < 8; j++) acc[i][j] = 0ull;

    for (int k0 = 0; k0 < 1024; k0 += 16) {
        // ---- load A tile 128x16 (transposed into smem), optional col scale
        #pragma unroll
        for (int i = 0; i < 2; i++) {
            int idx = tid + i * 256;
            int r   = idx >> 2;            // 0..127
            int c4  = (idx & 3) << 2;      // 0,4,8,12
            float4 v = *(const float4*)&A[(size_t)(brow + r) * 1024 + k0 + c4];
            if (HAS_SCALE) {
                float4 sv = *(const float4*)&scaleA[batch * 1024 + k0 + c4];
                v.x *= sv.x; v.y *= sv.y; v.z *= sv.z; v.w *= sv.w;
            }
            As[c4 + 0][r] = v.x; As[c4 + 1][r] = v.y;
            As[c4 + 2][r] = v.z; As[c4 + 3][r] = v.w;
        }
        // ---- load W tile 16x128, stored duplicated for f32x2 broadcast pairs
        #pragma unroll
        for (int i = 0; i < 2; i++) {
            int idx = tid + i * 256;
            int r   = idx >> 5;            // 0..15
            int c4  = (idx & 31) << 2;     // 0..124
            float4 v = *(const float4*)&W[(size_t)(k0 + r) * 1024 + bcol + c4];
            *(float4*)&Ws2[r][2 * c4]     = make_float4(v.x, v.x, v.y, v.y);
            *(float4*)&Ws2[r][2 * c4 + 4] = make_float4(v.z, v.z, v.w, v.w);
        }
        __syncthreads();

        #pragma unroll
        for (int k = 0; k < 16; k++) {
            const ull* As64 = (const ull*)&As[k][0];
            const ull* Ws64 = (const ull*)&Ws2[k][0];
            ulonglong2 ap01 = *(const ulonglong2*)&As64[ty * 2];        // rows ty*4..+3
            ulonglong2 ap23 = *(const ulonglong2*)&As64[32 + ty * 2];   // rows 64+ty*4..+3
            ulonglong2 b01  = *(const ulonglong2*)&Ws64[tx * 4];
            ulonglong2 b23  = *(const ulonglong2*)&Ws64[tx * 4 + 2];
            ulonglong2 b45  = *(const ulonglong2*)&Ws64[64 + tx * 4];
            ulonglong2 b67  = *(const ulonglong2*)&Ws64[64 + tx * 4 + 2];
            ull ap[4] = {ap01.x, ap01.y, ap23.x, ap23.y};
            ull bb[8] = {b01.x, b01.y, b23.x, b23.y, b45.x, b45.y, b67.x, b67.y};
            #pragma unroll
            for (int ip = 0; ip < 4; ip++)
                #pragma unroll
                for (int j = 0; j < 8; j++)
                    ffma2(acc[ip][j], ap[ip], bb[j]);
        }
        __syncthreads();
    }

    // ---- epilogue
    #pragma unroll
    for (int ip = 0; ip < 4; ip++) {
        int r0 = (ip < 2) ? (ty * 4 + 2 * ip) : (64 + ty * 4 + 2 * (ip - 2));
        #pragma unroll
        for (int hf = 0; hf < 2; hf++) {
            int r = brow + r0 + hf;
            #pragma unroll
            for (int g = 0; g < 2; g++) {
                int c = bcol + g * 64 + tx * 4;
                const ull* a = &acc[ip][g * 4];
                float4 v;
                v.x = hf ? hi32(a[0]) : lo32(a[0]);
                v.y = hf ? hi32(a[1]) : lo32(a[1]);
                v.z = hf ? hi32(a[2]) : lo32(a[2]);
                v.w = hf ? hi32(a[3]) : lo32(a[3]);
                float4 bi = *(const float4*)&bias[c];
                v.x += bi.x; v.y += bi.y; v.z += bi.z; v.w += bi.w;
                if (HAS_ADD) {
                    float4 ad = *(const float4*)&addC[(size_t)r * 1024 + c];
                    v.x += ad.x; v.y += ad.y; v.z += ad.z; v.w += ad.w;
                }
                *(float4*)&C[(size_t)r * 1024 + c] = v;
            }
        }
    }
}

// =====================================================================
// score[b,h,s] = (X[b,s,:] (* mul[b,:]) . Wa[:,h] + ba[h]) * 0.125 + mask[b,s]
// One warp per (b,s) row. Wa transposed into 64KB dynamic smem.
// =====================================================================
__global__ __launch_bounds__(256)
void score_kernel(const float* __restrict__ X, const float* __restrict__ Wa,
                  const float* __restrict__ ba, const float* __restrict__ mask,
                  const float* __restrict__ mul, float* __restrict__ score)
{
    extern __shared__ float WaS[];  // [16][1024] transposed: WaS[h*1024+d]
    for (int idx = threadIdx.x; idx < 16 * 1024; idx += 256) {
        int d = idx >> 4, h = idx & 15;
        WaS[h * 1024 + d] = Wa[idx];
    }
    __syncthreads();

    int warp = threadIdx.x >> 5, lane = threadIdx.x & 31;
    int m = blockIdx.x * 8 + warp;
    int b = m >> 13, s = m & 8191;
    const float* xrow = X + (size_t)m * 1024;
    const float* mrow = mul ? (mul + b * 1024) : (const float*)0;

    float acc[16];
    #pragma unroll
    for (int h = 0; h < 16; h++) acc[h] = 0.f;

    #pragma unroll
    for (int it = 0; it < 8; it++) {
        int d = it * 128 + lane * 4;
        float4 x = *(const float4*)&xrow[d];
        if (mrow) {
            float4 mu = *(const float4*)&mrow[d];
            x.x *= mu.x; x.y *= mu.y; x.z *= mu.z; x.w *= mu.w;
        }
        #pragma unroll
        for (int h = 0; h < 16; h++) {
            float4 w = *(const float4*)&WaS[h * 1024 + d];
            acc[h] += x.x * w.x + x.y * w.y + x.z * w.z + x.w * w.w;
        }
    }
    #pragma unroll
    for (int off = 16; off > 0; off >>= 1)
        #pragma unroll
        for (int h = 0; h < 16; h++)
            acc[h] += __shfl_xor_sync(0xffffffffu, acc[h], off);

    if (lane == 0) {
        float mk = mask[(b << 13) + s];
        #pragma unroll
        for (int h = 0; h < 16; h++)
            score[(size_t)(b * 16 + h) * 8192 + s] = (acc[h] + ba[h]) * 0.125f + mk;
    }
}

// =====================================================================
// pooled[b, h*64+dh] = (Σ_s softmax(score[b,h,:])[s] * X[b,s,h*64+dh]) (* mul[b,h*64+dh])
// One block per (b,h). mul applied once at the end (pooled_q is constant over s).
// =====================================================================
__global__ __launch_bounds__(256)
void softmax_pool_kernel(const float* __restrict__ score, const float* __restrict__ X,
                         const float* __restrict__ mul, float* __restrict__ pooled)
{
    int bh = blockIdx.x;
    int b = bh >> 4, h = bh & 15;
    const float* sc = score + ((size_t)bh << 13);
    int tid = threadIdx.x;

    __shared__ float red[256];
    float mx = -3.0e38f;
    for (int s = tid; s < 8192; s += 256) mx = fmaxf(mx, sc[s]);
    red[tid] = mx;
    __syncthreads();
    for (int st = 128; st > 0; st >>= 1) {
        if (tid < st) red[tid] = fmaxf(red[tid], red[tid + st]);
        __syncthreads();
    }
    mx = red[0];

    float acc[64];
    #pragma unroll
    for (int j = 0; j < 64; j++) acc[j] = 0.f;
    float sumw = 0.f;

    for (int s = tid; s < 8192; s += 256) {
        float w = expf(sc[s] - mx);
        sumw += w;
        const float4* xr = (const float4*)(X + ((size_t)(b * 8192 + s)) * 1024 + h * 64);
        #pragma unroll
        for (int j = 0; j < 16; j++) {
            float4 v = xr[j];
            acc[4 * j + 0] += w * v.x; acc[4 * j + 1] += w * v.y;
            acc[4 * j + 2] += w * v.z; acc[4 * j + 3] += w * v.w;
        }
    }
    #pragma unroll
    for (int off = 16; off > 0; off >>= 1) {
        sumw += __shfl_xor_sync(0xffffffffu, sumw, off);
        #pragma unroll
        for (int j = 0; j < 64; j++)
            acc[j] += __shfl_xor_sync(0xffffffffu, acc[j], off);
    }

    __shared__ float sacc[8][64];
    __shared__ float ssum[8];
    int warp = tid >> 5, lane = tid & 31;
    if (lane == 0) ssum[warp] = sumw;
    #pragma unroll
    for (int j = 0; j < 64; j++)
        if ((j & 31) == lane) sacc[warp][j] = acc[j];
    __syncthreads();

    if (tid < 64) {
        float tot = 0.f, Z = 0.f;
        #pragma unroll
        for (int w = 0; w < 8; w++) { tot += sacc[w][tid]; Z += ssum[w]; }
        float r = tot / Z;
        if (mul) r *= mul[b * 1024 + h * 64 + tid];
        pooled[b * 1024 + h * 64 + tid] = r;
    }
}

// =====================================================================
extern "C" void kernel_launch(void* const* d_in, const int* in_sizes, int n_in,
                              void* d_out, int out_size)
{
    const float* hs   = (const float*)d_in[0];
    const float* mask = (const float*)d_in[1];
    const float* Wq   = (const float*)d_in[2];
    const float* bq   = (const float*)d_in[3];
    const float* Wqa  = (const float*)d_in[4];
    const float* bqa  = (const float*)d_in[5];
    const float* Wk   = (const float*)d_in[6];
    const float* bk   = (const float*)d_in[7];
    const float* Wka  = (const float*)d_in[8];
    const float* bka  = (const float*)d_in[9];
    const float* Wt   = (const float*)d_in[10];
    const float* bt   = (const float*)d_in[11];
    float* out = (float*)d_out;

    float *mq, *mk, *sco, *pq, *pk;
    cudaGetSymbolAddress((void**)&mq, g_mq);
    cudaGetSymbolAddress((void**)&mk, g_mk);
    cudaGetSymbolAddress((void**)&sco, g_score);
    cudaGetSymbolAddress((void**)&pq, g_pq);
    cudaGetSymbolAddress((void**)&pk, g_pk);

    cudaFuncSetAttribute(score_kernel, cudaFuncAttributeMaxDynamicSharedMemorySize, 65536);

    dim3 gg(8, 256);  // N/128, M/128

    // mixed_q = hs@Wq + bq ; mixed_k = hs@Wk + bk
    sgemm_kernel<false, false><<<gg, 256>>>(hs, Wq, bq, nullptr, nullptr, mq);
    sgemm_kernel<false, false><<<gg, 256>>>(hs, Wk, bk, nullptr, nullptr, mk);

    // q attention pooling
    score_kernel<<<4096, 256, 65536>>>(mq, Wqa, bqa, mask, nullptr, sco);
    softmax_pool_kernel<<<64, 256>>>(sco, mq, nullptr, pq);

    // k attention pooling (mixed_qk = mixed_k * pooled_q, never materialized)
    score_kernel<<<4096, 256, 65536>>>(mk, Wka, bka, mask, pq, sco);
    softmax_pool_kernel<<<64, 256>>>(sco, mk, pq, pk);

    // out = (mixed_q * pooled_k) @ Wt + bt + mixed_q
    sgemm_kernel<true, true><<<gg, 256>>>(mq, Wt, bt, pk, mq, out);
}

// round 6
// speedup vs baseline: 2.4393x; 2.4393x over previous
#include <cuda_runtime.h>
#include <cuda_bf16.h>
#include <math.h>
#include <stdint.h>

#define B_  4
#define S_  8192
#define D_  1024
#define H_  16
#define M_  (B_*S_)

// ---------------- scratch (device globals; no cudaMalloc) ----------------
__device__ float g_mq[(size_t)M_ * D_];                 // mixed_q  [B,S,D]
__device__ float g_mk[(size_t)M_ * D_];                 // mixed_k  [B,S,D]
__device__ __nv_bfloat16 g_Ah[(size_t)M_ * D_];         // A hi split
__device__ __nv_bfloat16 g_Al[(size_t)M_ * D_];         // A lo split
__device__ __nv_bfloat16 g_Bqk_hi[2048 * 1024];         // [n, k]  (Wq cols | Wk cols)
__device__ __nv_bfloat16 g_Bqk_lo[2048 * 1024];
__device__ __nv_bfloat16 g_Bt_hi[1024 * 1024];          // Wt^T
__device__ __nv_bfloat16 g_Bt_lo[1024 * 1024];
__device__ float g_score[B_ * H_ * S_];
__device__ float g_mxv[64];
__device__ float g_part[512 * 65];
__device__ float g_pq[B_ * D_];
__device__ float g_pk[B_ * D_];

// ---------------- helpers (sm_80-era PTX only: portable to sm_103) ----------------
__device__ __forceinline__ uint32_t smem_u32(const void* p) {
    uint32_t a;
    asm("{ .reg .u64 t; cvta.to.shared.u64 t, %1; cvt.u32.u64 %0, t; }" : "=r"(a) : "l"(p));
    return a;
}
__device__ __forceinline__ void cp16(uint32_t dst, const void* src) {
    asm volatile("cp.async.cg.shared.global [%0], [%1], 16;" :: "r"(dst), "l"(src));
}
__device__ __forceinline__ void ldsm4(uint32_t* r, uint32_t addr) {
    asm volatile("ldmatrix.sync.aligned.m8n8.x4.shared.b16 {%0,%1,%2,%3}, [%4];"
                 : "=r"(r[0]), "=r"(r[1]), "=r"(r[2]), "=r"(r[3]) : "r"(addr));
}
__device__ __forceinline__ void mma16816(float* d, const uint32_t* a, const uint32_t* b) {
    asm volatile("mma.sync.aligned.m16n8k16.row.col.f32.bf16.bf16.f32 "
                 "{%0,%1,%2,%3}, {%4,%5,%6,%7}, {%8,%9}, {%0,%1,%2,%3};"
                 : "+f"(d[0]), "+f"(d[1]), "+f"(d[2]), "+f"(d[3])
                 : "r"(a[0]), "r"(a[1]), "r"(a[2]), "r"(a[3]), "r"(b[0]), "r"(b[1]));
}
__device__ __forceinline__ uint32_t split_pack(float x, float y, uint32_t& lo) {
    __nv_bfloat16 hx = __float2bfloat16(x), hy = __float2bfloat16(y);
    __nv_bfloat16 lx = __float2bfloat16(x - __bfloat162float(hx));
    __nv_bfloat16 ly = __float2bfloat16(y - __bfloat162float(hy));
    lo = (uint32_t)__bfloat16_as_ushort(lx) | ((uint32_t)__bfloat16_as_ushort(ly) << 16);
    return (uint32_t)__bfloat16_as_ushort(hx) | ((uint32_t)__bfloat16_as_ushort(hy) << 16);
}

// =====================================================================
// Weight prep: out[n][k] = split(W[k][n]) as bf16 hi/lo (transpose+split)
// =====================================================================
__global__ void wprep_kernel(const float* __restrict__ W,
                             __nv_bfloat16* __restrict__ hi, __nv_bfloat16* __restrict__ lo)
{
    __shared__ float t[32][33];
    int n0 = blockIdx.x * 32, k0 = blockIdx.y * 32;
    int tx = threadIdx.x, ty = threadIdx.y;
    for (int i = ty; i < 32; i += 8)
        t[i][tx] = W[(size_t)(k0 + i) * 1024 + n0 + tx];
    __syncthreads();
    for (int i = ty; i < 32; i += 8) {
        float v = t[tx][i];  // W[k0+tx][n0+i]
        __nv_bfloat16 h = __float2bfloat16(v);
        __nv_bfloat16 l = __float2bfloat16(v - __bfloat162float(h));
        hi[(size_t)(n0 + i) * 1024 + k0 + tx] = h;
        lo[(size_t)(n0 + i) * 1024 + k0 + tx] = l;
    }
}

// =====================================================================
// A split: hi/lo bf16 of X (optionally scaled per (batch, d) by scaleK)
// one float4 per thread
// =====================================================================
template<bool SCALE>
__global__ __launch_bounds__(256)
void asplit_kernel(const float* __restrict__ X, const float* __restrict__ scaleK,
                   __nv_bfloat16* __restrict__ hi, __nv_bfloat16* __restrict__ lo)
{
    size_t i = (size_t)blockIdx.x * 256 + threadIdx.x;   // float4 index
    float4 v = ((const float4*)X)[i];
    if (SCALE) {
        int d = (int)((i << 2) & 1023);
        int batch = (int)(i >> 21);                      // i/(8192*256)
        float4 sv = *(const float4*)&scaleK[batch * 1024 + d];
        v.x *= sv.x; v.y *= sv.y; v.z *= sv.z; v.w *= sv.w;
    }
    uint32_t l0, l1;
    uint32_t h0 = split_pack(v.x, v.y, l0);
    uint32_t h1 = split_pack(v.z, v.w, l1);
    ((uint2*)hi)[i] = make_uint2(h0, h1);
    ((uint2*)lo)[i] = make_uint2(l0, l1);
}

// =====================================================================
// HMMA bf16x3 GEMM:  C = Afp32 @ W + bias (+addC), via
//   Ah*Bh + Al*Bh + Ah*Bl  accumulated in one K'=3072 sweep.
// CTA tile 128x128, 8 warps (2M x 4N), warp tile 64x32, BK=32, 3-stage cp.async.
// SMEM per stage: A 128x40 bf16 (10240B) + B 128x40 bf16 -> 20480B; 3 stages = 61440B.
// =====================================================================
__device__ __forceinline__ void issue_stage(
    int s, uint32_t smb, int brow, int bcol,
    const __nv_bfloat16* const* Aseg, const __nv_bfloat16* const* Bseg,
    int crow, int cc8)
{
    int st = s % 3;
    int kg = s << 5;
    int seg = kg >> 10;
    int k0 = kg & 1023;
    const __nv_bfloat16* Ab = Aseg[seg];
    const __nv_bfloat16* Bb = Bseg[seg];
    uint32_t As = smb + (uint32_t)st * 20480u;
    uint32_t Bs = As + 10240u;
    #pragma unroll
    for (int i = 0; i < 2; i++) {
        int r = crow + i * 64;
        cp16(As + (uint32_t)(r * 80 + cc8 * 2), Ab + (size_t)(brow + r) * 1024 + k0 + cc8);
        cp16(Bs + (uint32_t)(r * 80 + cc8 * 2), Bb + (size_t)(bcol + r) * 1024 + k0 + cc8);
    }
    asm volatile("cp.async.commit_group;" ::: "memory");
}

template<bool DUAL, bool ADD>
__global__ __launch_bounds__(256, 1)
void hmma_gemm_kernel(const __nv_bfloat16* __restrict__ Ah, const __nv_bfloat16* __restrict__ Al,
                      const __nv_bfloat16* __restrict__ Bh, const __nv_bfloat16* __restrict__ Bl,
                      const float* __restrict__ bias0, const float* __restrict__ bias1,
                      const float* __restrict__ addC,
                      float* __restrict__ C0, float* __restrict__ C1)
{
    extern __shared__ char smraw[];
    const uint32_t smb = smem_u32(smraw);
    const int tid = threadIdx.x, lane = tid & 31, wid = tid >> 5;
    const int wr = wid & 1, wc = wid >> 1;
    const int brow = blockIdx.y * 128, bcol = blockIdx.x * 128;

    const __nv_bfloat16* Aseg[3] = {Ah, Al, Ah};
    const __nv_bfloat16* Bseg[3] = {Bh, Bh, Bl};

    float acc[4][4][4];
    #pragma unroll
    for (int mt = 0; mt < 4; mt++)
        #pragma unroll
        for (int nt = 0; nt < 4; nt++)
            #pragma unroll
            for (int j = 0; j < 4; j++) acc[mt][nt][j] = 0.f;

    const int crow = tid >> 2;       // 0..63
    const int cc8  = (tid & 3) * 8;  // element offset within 32-wide k slice

    issue_stage(0, smb, brow, bcol, Aseg, Bseg, crow, cc8);
    issue_stage(1, smb, brow, bcol, Aseg, Bseg, crow, cc8);

    const int am  = wr * 64 + (lane & 15);
    const int akh = (lane >> 4) * 8;
    const int g   = lane >> 3;
    const int bn  = wc * 32 + (lane & 7) + (g >> 1) * 8;
    const int bkh = (g & 1) * 8;

    for (int s = 0; s < 96; s++) {
        asm volatile("cp.async.wait_group 1;" ::: "memory");
        __syncthreads();
        if (s + 2 < 96) issue_stage(s + 2, smb, brow, bcol, Aseg, Bseg, crow, cc8);
        else            asm volatile("cp.async.commit_group;" ::: "memory");

        uint32_t Asb = smb + (uint32_t)(s % 3) * 20480u;
        uint32_t Bsb = Asb + 10240u;
        #pragma unroll
        for (int kk = 0; kk < 2; kk++) {
            const int k = kk * 16;
            uint32_t a[4][4], b[2][4];
            #pragma unroll
            for (int mt = 0; mt < 4; mt++)
                ldsm4(a[mt], Asb + (uint32_t)((am + mt * 16) * 80 + (k + akh) * 2));
            #pragma unroll
            for (int bt = 0; bt < 2; bt++)
                ldsm4(b[bt], Bsb + (uint32_t)((bn + bt * 16) * 80 + (k + bkh) * 2));
            #pragma unroll
            for (int mt = 0; mt < 4; mt++)
                #pragma unroll
                for (int nt = 0; nt < 4; nt++)
                    mma16816(acc[mt][nt], a[mt], &b[nt >> 1][(nt & 1) * 2]);
        }
    }

    // ---- epilogue
    const float* bias = bias0;
    float* Cd = C0;
    int ceff = bcol;
    if (DUAL && bcol >= 1024) { bias = bias1; Cd = C1; ceff = bcol - 1024; }

    #pragma unroll
    for (int mt = 0; mt < 4; mt++) {
        const int r = brow + wr * 64 + mt * 16 + (lane >> 2);
        #pragma unroll
        for (int nt = 0; nt < 4; nt++) {
            const int c = ceff + wc * 32 + nt * 8 + (lane & 3) * 2;
            float2 bi = *(const float2*)&bias[c];
            float2 v0 = make_float2(acc[mt][nt][0] + bi.x, acc[mt][nt][1] + bi.y);
            float2 v1 = make_float2(acc[mt][nt][2] + bi.x, acc[mt][nt][3] + bi.y);
            if (ADD) {
                float2 a0 = *(const float2*)&addC[(size_t)r * 1024 + c];
                float2 a1 = *(const float2*)&addC[(size_t)(r + 8) * 1024 + c];
                v0.x += a0.x; v0.y += a0.y; v1.x += a1.x; v1.y += a1.y;
            }
            *(float2*)&Cd[(size_t)r * 1024 + c] = v0;
            *(float2*)&Cd[(size_t)(r + 8) * 1024 + c] = v1;
        }
    }
}

// =====================================================================
// score[b,h,s] = (X[b,s,:] (* mul[b,:]) . Wa[:,h] + ba[h]) * 0.125 + mask[b,s]
// =====================================================================
__global__ __launch_bounds__(256)
void score_kernel(const float* __restrict__ X, const float* __restrict__ Wa,
                  const float* __restrict__ ba, const float* __restrict__ mask,
                  const float* __restrict__ mul, float* __restrict__ score)
{
    extern __shared__ float WaS[];  // [16][1024] transposed
    for (int idx = threadIdx.x; idx < 16 * 1024; idx += 256) {
        int d = idx >> 4, h = idx & 15;
        WaS[h * 1024 + d] = Wa[idx];
    }
    __syncthreads();

    int warp = threadIdx.x >> 5, lane = threadIdx.x & 31;
    int m = blockIdx.x * 8 + warp;
    int b = m >> 13, s = m & 8191;
    const float* xrow = X + (size_t)m * 1024;
    const float* mrow = mul ? (mul + b * 1024) : (const float*)0;

    float acc[16];
    #pragma unroll
    for (int h = 0; h < 16; h++) acc[h] = 0.f;

    #pragma unroll
    for (int it = 0; it < 8; it++) {
        int d = it * 128 + lane * 4;
        float4 x = *(const float4*)&xrow[d];
        if (mrow) {
            float4 mu = *(const float4*)&mrow[d];
            x.x *= mu.x; x.y *= mu.y; x.z *= mu.z; x.w *= mu.w;
        }
        #pragma unroll
        for (int h = 0; h < 16; h++) {
            float4 w = *(const float4*)&WaS[h * 1024 + d];
            acc[h] += x.x * w.x + x.y * w.y + x.z * w.z + x.w * w.w;
        }
    }
    #pragma unroll
    for (int off = 16; off > 0; off >>= 1)
        #pragma unroll
        for (int h = 0; h < 16; h++)
            acc[h] += __shfl_xor_sync(0xffffffffu, acc[h], off);

    if (lane == 0) {
        float mk = mask[(b << 13) + s];
        #pragma unroll
        for (int h = 0; h < 16; h++)
            score[(size_t)(b * 16 + h) * 8192 + s] = (acc[h] + ba[h]) * 0.125f + mk;
    }
}

// =====================================================================
// Softmax pooling, 3-phase for full-chip parallelism
// =====================================================================
__global__ void score_max_kernel(const float* __restrict__ sc, float* __restrict__ mx)
{
    __shared__ float red[256];
    int bh = blockIdx.x, tid = threadIdx.x;
    const float* p = sc + ((size_t)bh << 13);
    float m = -3.0e38f;
    for (int s = tid; s < 8192; s += 256) m = fmaxf(m, p[s]);
    red[tid] = m; __syncthreads();
    for (int st = 128; st > 0; st >>= 1) {
        if (tid < st) red[tid] = fmaxf(red[tid], red[tid + st]);
        __syncthreads();
    }
    if (tid == 0) mx[bh] = red[0];
}

__global__ __launch_bounds__(256)
void pool_partial_kernel(const float* __restrict__ score, const float* __restrict__ X,
                         const float* __restrict__ mxbuf, float* __restrict__ part)
{
    int bh = blockIdx.x, ch = blockIdx.y;
    int b = bh >> 4, h = bh & 15;
    const float* sc = score + ((size_t)bh << 13) + (ch << 10);
    int tid = threadIdx.x;
    float mx = mxbuf[bh];
    float acc[64];
    #pragma unroll
    for (int j = 0; j < 64; j++) acc[j] = 0.f;
    float sumw = 0.f;
    for (int s = tid; s < 1024; s += 256) {
        float w = expf(sc[s] - mx);
        sumw += w;
        const float4* xr = (const float4*)(X + ((size_t)((b << 13) + (ch << 10) + s)) * 1024 + h * 64);
        #pragma unroll
        for (int j = 0; j < 16; j++) {
            float4 v = xr[j];
            acc[4*j+0] += w*v.x; acc[4*j+1] += w*v.y;
            acc[4*j+2] += w*v.z; acc[4*j+3] += w*v.w;
        }
    }
    #pragma unroll
    for (int off = 16; off > 0; off >>= 1) {
        sumw += __shfl_xor_sync(0xffffffffu, sumw, off);
        #pragma unroll
        for (int j = 0; j < 64; j++)
            acc[j] += __shfl_xor_sync(0xffffffffu, acc[j], off);
    }
    __shared__ float sacc[8][64];
    __shared__ float ssum[8];
    int warp = tid >> 5, lane = tid & 31;
    if (lane == 0) ssum[warp] = sumw;
    #pragma unroll
    for (int j = 0; j < 64; j++)
        if ((j & 31) == lane) sacc[warp][j] = acc[j];
    __syncthreads();
    if (tid < 64) {
        float tot = 0.f, Z = 0.f;
        #pragma unroll
        for (int w = 0; w < 8; w++) { tot += sacc[w][tid]; Z += ssum[w]; }
        float* p = part + (size_t)(bh * 8 + ch) * 65;
        p[tid] = tot;
        if (tid == 0) p[64] = Z;
    }
}

__global__ void pool_combine_kernel(const float* __restrict__ part, const float* __restrict__ mul,
                                    float* __restrict__ pooled)
{
    int bh = blockIdx.x, tid = threadIdx.x;  // block 64
    int b = bh >> 4, h = bh & 15;
    float tot = 0.f, Z = 0.f;
    #pragma unroll
    for (int ch = 0; ch < 8; ch++) {
        const float* p = part + (size_t)(bh * 8 + ch) * 65;
        tot += p[tid]; Z += p[64];
    }
    float r = tot / Z;
    if (mul) r *= mul[b * 1024 + h * 64 + tid];
    pooled[b * 1024 + h * 64 + tid] = r;
}

// =====================================================================
extern "C" void kernel_launch(void* const* d_in, const int* in_sizes, int n_in,
                              void* d_out, int out_size)
{
    const float* hs   = (const float*)d_in[0];
    const float* mask = (const float*)d_in[1];
    const float* Wq   = (const float*)d_in[2];
    const float* bq   = (const float*)d_in[3];
    const float* Wqa  = (const float*)d_in[4];
    const float* bqa  = (const float*)d_in[5];
    const float* Wk   = (const float*)d_in[6];
    const float* bk   = (const float*)d_in[7];
    const float* Wka  = (const float*)d_in[8];
    const float* bka  = (const float*)d_in[9];
    const float* Wt   = (const float*)d_in[10];
    const float* bt   = (const float*)d_in[11];
    float* out = (float*)d_out;

    float *mq, *mk, *sco, *mx, *part, *pq, *pk;
    __nv_bfloat16 *Ah, *Al, *bqk_hi, *bqk_lo, *btp_hi, *btp_lo;
    cudaGetSymbolAddress((void**)&mq, g_mq);
    cudaGetSymbolAddress((void**)&mk, g_mk);
    cudaGetSymbolAddress((void**)&sco, g_score);
    cudaGetSymbolAddress((void**)&mx, g_mxv);
    cudaGetSymbolAddress((void**)&part, g_part);
    cudaGetSymbolAddress((void**)&pq, g_pq);
    cudaGetSymbolAddress((void**)&pk, g_pk);
    cudaGetSymbolAddress((void**)&Ah, g_Ah);
    cudaGetSymbolAddress((void**)&Al, g_Al);
    cudaGetSymbolAddress((void**)&bqk_hi, g_Bqk_hi);
    cudaGetSymbolAddress((void**)&bqk_lo, g_Bqk_lo);
    cudaGetSymbolAddress((void**)&btp_hi, g_Bt_hi);
    cudaGetSymbolAddress((void**)&btp_lo, g_Bt_lo);

    const int GSMEM = 61440;
    cudaFuncSetAttribute(hmma_gemm_kernel<true,  false>,
                         cudaFuncAttributeMaxDynamicSharedMemorySize, GSMEM);
    cudaFuncSetAttribute(hmma_gemm_kernel<false, true>,
                         cudaFuncAttributeMaxDynamicSharedMemorySize, GSMEM);
    cudaFuncSetAttribute(score_kernel, cudaFuncAttributeMaxDynamicSharedMemorySize, 65536);

    // ---- weight prep: transpose + bf16 hi/lo split
    dim3 wblk(32, 8), wgrd(32, 32);
    wprep_kernel<<<wgrd, wblk>>>(Wq, bqk_hi, bqk_lo);
    wprep_kernel<<<wgrd, wblk>>>(Wk, bqk_hi + 1024 * 1024, bqk_lo + 1024 * 1024);
    wprep_kernel<<<wgrd, wblk>>>(Wt, btp_hi, btp_lo);

    // ---- split hs into bf16 hi/lo
    asplit_kernel<false><<<32768, 256>>>(hs, nullptr, Ah, Al);

    // ---- fused mixed_q / mixed_k GEMM (N=2048 over [Wq|Wk])
    hmma_gemm_kernel<true, false><<<dim3(16, 256), 256, GSMEM>>>(
        Ah, Al, bqk_hi, bqk_lo, bq, bk, nullptr, mq, mk);

    // ---- q attention pooling
    score_kernel<<<4096, 256, 65536>>>(mq, Wqa, bqa, mask, nullptr, sco);
    score_max_kernel<<<64, 256>>>(sco, mx);
    pool_partial_kernel<<<dim3(64, 8), 256>>>(sco, mq, mx, part);
    pool_combine_kernel<<<64, 64>>>(part, nullptr, pq);

    // ---- k attention pooling (mixed_qk = mixed_k * pooled_q, never materialized)
    score_kernel<<<4096, 256, 65536>>>(mk, Wka, bka, mask, pq, sco);
    score_max_kernel<<<64, 256>>>(sco, mx);
    pool_partial_kernel<<<dim3(64, 8), 256>>>(sco, mk, mx, part);
    pool_combine_kernel<<<64, 64>>>(part, pq, pk);

    // ---- split (mixed_q * pooled_k) into bf16 hi/lo
    asplit_kernel<true><<<32768, 256>>>(mq, pk, Ah, Al);

    // ---- out = (mixed_q * pooled_k) @ Wt + bt + mixed_q
    hmma_gemm_kernel<false, true><<<dim3(8, 256), 256, GSMEM>>>(
        Ah, Al, btp_hi, btp_lo, bt, nullptr, mq, out, nullptr);
}

// round 10
// speedup vs baseline: 2.8180x; 1.1552x over previous
#include <cuda_runtime.h>
#include <cuda_bf16.h>
#include <math.h>
#include <stdint.h>

#define B_  4
#define S_  8192
#define D_  1024
#define H_  16
#define M_  (B_*S_)

// ---------------- scratch (device globals; no cudaMalloc) ----------------
__device__ float g_mq[(size_t)M_ * D_];                 // mixed_q  [B,S,D]
__device__ float g_mk[(size_t)M_ * D_];                 // mixed_k  [B,S,D]
__device__ __nv_bfloat16 g_Ah[(size_t)M_ * D_];         // A hi split
__device__ __nv_bfloat16 g_Al[(size_t)M_ * D_];         // A lo split
__device__ __nv_bfloat16 g_Bqk_hi[2048 * 1024];         // [n, k]  (Wq cols | Wk cols)
__device__ __nv_bfloat16 g_Bqk_lo[2048 * 1024];
__device__ __nv_bfloat16 g_Bt_hi[1024 * 1024];          // Wt^T
__device__ __nv_bfloat16 g_Bt_lo[1024 * 1024];
__device__ float g_score[B_ * H_ * S_];
__device__ float g_mxv[64];
__device__ float g_part[512 * 65];
__device__ float g_pq[B_ * D_];
__device__ float g_pk[B_ * D_];

// ---------------- helpers (sm_80-era PTX only: portable to sm_103) ----------------
__device__ __forceinline__ uint32_t smem_u32(const void* p) {
    uint32_t a;
    asm("{ .reg .u64 t; cvta.to.shared.u64 t, %1; cvt.u32.u64 %0, t; }" : "=r"(a) : "l"(p));
    return a;
}
__device__ __forceinline__ void cp16(uint32_t dst, const void* src) {
    asm volatile("cp.async.cg.shared.global [%0], [%1], 16;" :: "r"(dst), "l"(src));
}
__device__ __forceinline__ void ldsm4(uint32_t* r, uint32_t addr) {
    asm volatile("ldmatrix.sync.aligned.m8n8.x4.shared.b16 {%0,%1,%2,%3}, [%4];"
                 : "=r"(r[0]), "=r"(r[1]), "=r"(r[2]), "=r"(r[3]) : "r"(addr));
}
__device__ __forceinline__ void mma16816(float* d, const uint32_t* a, const uint32_t* b) {
    asm volatile("mma.sync.aligned.m16n8k16.row.col.f32.bf16.bf16.f32 "
                 "{%0,%1,%2,%3}, {%4,%5,%6,%7}, {%8,%9}, {%0,%1,%2,%3};"
                 : "+f"(d[0]), "+f"(d[1]), "+f"(d[2]), "+f"(d[3])
                 : "r"(a[0]), "r"(a[1]), "r"(a[2]), "r"(a[3]), "r"(b[0]), "r"(b[1]));
}
__device__ __forceinline__ uint32_t split_pack(float x, float y, uint32_t& lo) {
    __nv_bfloat16 hx = __float2bfloat16(x), hy = __float2bfloat16(y);
    __nv_bfloat16 lx = __float2bfloat16(x - __bfloat162float(hx));
    __nv_bfloat16 ly = __float2bfloat16(y - __bfloat162float(hy));
    lo = (uint32_t)__bfloat16_as_ushort(lx) | ((uint32_t)__bfloat16_as_ushort(ly) << 16);
    return (uint32_t)__bfloat16_as_ushort(hx) | ((uint32_t)__bfloat16_as_ushort(hy) << 16);
}

// =====================================================================
// Weight prep: out[n][k] = split(W[k][n]) as bf16 hi/lo (transpose+split)
// =====================================================================
__global__ void wprep_kernel(const float* __restrict__ W,
                             __nv_bfloat16* __restrict__ hi, __nv_bfloat16* __restrict__ lo)
{
    __shared__ float t[32][33];
    int n0 = blockIdx.x * 32, k0 = blockIdx.y * 32;
    int tx = threadIdx.x, ty = threadIdx.y;
    for (int i = ty; i < 32; i += 8)
        t[i][tx] = W[(size_t)(k0 + i) * 1024 + n0 + tx];
    __syncthreads();
    for (int i = ty; i < 32; i += 8) {
        float v = t[tx][i];  // W[k0+tx][n0+i]
        __nv_bfloat16 h = __float2bfloat16(v);
        __nv_bfloat16 l = __float2bfloat16(v - __bfloat162float(h));
        hi[(size_t)(n0 + i) * 1024 + k0 + tx] = h;
        lo[(size_t)(n0 + i) * 1024 + k0 + tx] = l;
    }
}

// =====================================================================
// A split: hi/lo bf16 of X (optionally scaled per (batch, d) by scaleK)
// =====================================================================
template<bool SCALE>
__global__ __launch_bounds__(256)
void asplit_kernel(const float* __restrict__ X, const float* __restrict__ scaleK,
                   __nv_bfloat16* __restrict__ hi, __nv_bfloat16* __restrict__ lo)
{
    size_t i = (size_t)blockIdx.x * 256 + threadIdx.x;   // float4 index
    float4 v = ((const float4*)X)[i];
    if (SCALE) {
        int d = (int)((i << 2) & 1023);
        int batch = (int)(i >> 21);                      // i/(8192*256)
        float4 sv = *(const float4*)&scaleK[batch * 1024 + d];
        v.x *= sv.x; v.y *= sv.y; v.z *= sv.z; v.w *= sv.w;
    }
    uint32_t l0, l1;
    uint32_t h0 = split_pack(v.x, v.y, l0);
    uint32_t h1 = split_pack(v.z, v.w, l1);
    ((uint2*)hi)[i] = make_uint2(h0, h1);
    ((uint2*)lo)[i] = make_uint2(l0, l1);
}

// =====================================================================
// HMMA bf16x3 GEMM:  C = Afp32 @ W + bias (+addC), via
//   Ah*Bh + Al*Bh + Ah*Bl accumulated over one K'=3072 sweep.
// CTA tile 128x256, 8 warps (2M x 4N), warp tile 64x64, BK=32, 4-stage cp.async.
// SMEM/stage: A 128x80B (10240) + B 256x80B (20480) = 30720B; x4 = 122880B.
// Producer: rr=tid>>2 (0..63), cc=(tid&3)*8 elems; A rows {rr, rr+64} (2 cp16),
// B rows {rr, rr+64, rr+128, rr+192} (4 cp16) -> 24KB/stage exactly covered.
// =====================================================================
#define STAGE_BYTES 30720u
#define NSTAGE 4

__device__ __forceinline__ void issue_stage(
    int s, uint32_t smb, int brow, int bcol,
    const __nv_bfloat16* const* Aseg, const __nv_bfloat16* const* Bseg,
    int rr, int cc)
{
    const int st = s & (NSTAGE - 1);
    const int kg = s << 5;
    const int seg = kg >> 10;
    const int k0 = kg & 1023;
    const __nv_bfloat16* Ab = Aseg[seg];
    const __nv_bfloat16* Bb = Bseg[seg];
    uint32_t As = smb + (uint32_t)st * STAGE_BYTES;
    uint32_t Bs = As + 10240u;
    // A: 128 rows x 64B
    #pragma unroll
    for (int i = 0; i < 2; i++) {
        int r = rr + i * 64;
        cp16(As + (uint32_t)(r * 80 + cc * 2), Ab + (size_t)(brow + r) * 1024 + k0 + cc);
    }
    // B: 256 rows x 64B
    #pragma unroll
    for (int i = 0; i < 4; i++) {
        int r = rr + i * 64;
        cp16(Bs + (uint32_t)(r * 80 + cc * 2), Bb + (size_t)(bcol + r) * 1024 + k0 + cc);
    }
    asm volatile("cp.async.commit_group;" ::: "memory");
}

template<bool DUAL, bool ADD>
__global__ __launch_bounds__(256, 1)
void hmma_gemm_kernel(const __nv_bfloat16* __restrict__ Ah, const __nv_bfloat16* __restrict__ Al,
                      const __nv_bfloat16* __restrict__ Bh, const __nv_bfloat16* __restrict__ Bl,
                      const float* __restrict__ bias0, const float* __restrict__ bias1,
                      const float* __restrict__ addC,
                      float* __restrict__ C0, float* __restrict__ C1)
{
    extern __shared__ char smraw[];
    const uint32_t smb = smem_u32(smraw);
    const int tid = threadIdx.x, lane = tid & 31, wid = tid >> 5;
    const int wr = wid & 1, wc = wid >> 1;
    const int brow = blockIdx.y * 128, bcol = blockIdx.x * 256;

    const __nv_bfloat16* Aseg[3] = {Ah, Al, Ah};
    const __nv_bfloat16* Bseg[3] = {Bh, Bh, Bl};

    float acc[4][8][4];
    #pragma unroll
    for (int mt = 0; mt < 4; mt++)
        #pragma unroll
        for (int nt = 0; nt < 8; nt++)
            #pragma unroll
            for (int j = 0; j < 4; j++) acc[mt][nt][j] = 0.f;

    const int rr = tid >> 2;         // 0..63
    const int cc = (tid & 3) * 8;    // element offset: 0,8,16,24

    issue_stage(0, smb, brow, bcol, Aseg, Bseg, rr, cc);
    issue_stage(1, smb, brow, bcol, Aseg, Bseg, rr, cc);
    issue_stage(2, smb, brow, bcol, Aseg, Bseg, rr, cc);

    const int am  = wr * 64 + (lane & 15);
    const int akh = (lane >> 4) * 8;
    const int g   = lane >> 3;
    const int bn  = wc * 64 + (lane & 7) + (g >> 1) * 8;
    const int bkh = (g & 1) * 8;

    for (int s = 0; s < 96; s++) {
        asm volatile("cp.async.wait_group 2;" ::: "memory");
        __syncthreads();
        if (s + 3 < 96) issue_stage(s + 3, smb, brow, bcol, Aseg, Bseg, rr, cc);
        else            asm volatile("cp.async.commit_group;" ::: "memory");

        uint32_t Asb = smb + (uint32_t)(s & (NSTAGE - 1)) * STAGE_BYTES;
        uint32_t Bsb = Asb + 10240u;
        #pragma unroll
        for (int kk = 0; kk < 2; kk++) {
            const int k = kk * 16;
            uint32_t a[4][4], b[4][4];
            #pragma unroll
            for (int mt = 0; mt < 4; mt++)
                ldsm4(a[mt], Asb + (uint32_t)((am + mt * 16) * 80 + (k + akh) * 2));
            #pragma unroll
            for (int bt = 0; bt < 4; bt++)
                ldsm4(b[bt], Bsb + (uint32_t)((bn + bt * 16) * 80 + (k + bkh) * 2));
            #pragma unroll
            for (int mt = 0; mt < 4; mt++)
                #pragma unroll
                for (int nt = 0; nt < 8; nt++)
                    mma16816(acc[mt][nt], a[mt], &b[nt >> 1][(nt & 1) * 2]);
        }
    }

    // ---- epilogue
    const float* bias = bias0;
    float* Cd = C0;
    int ceff = bcol;
    if (DUAL && bcol >= 1024) { bias = bias1; Cd = C1; ceff = bcol - 1024; }

    #pragma unroll
    for (int mt = 0; mt < 4; mt++) {
        const int r = brow + wr * 64 + mt * 16 + (lane >> 2);
        #pragma unroll
        for (int nt = 0; nt < 8; nt++) {
            const int c = ceff + wc * 64 + nt * 8 + (lane & 3) * 2;
            float2 bi = *(const float2*)&bias[c];
            float2 v0 = make_float2(acc[mt][nt][0] + bi.x, acc[mt][nt][1] + bi.y);
            float2 v1 = make_float2(acc[mt][nt][2] + bi.x, acc[mt][nt][3] + bi.y);
            if (ADD) {
                float2 a0 = *(const float2*)&addC[(size_t)r * 1024 + c];
                float2 a1 = *(const float2*)&addC[(size_t)(r + 8) * 1024 + c];
                v0.x += a0.x; v0.y += a0.y; v1.x += a1.x; v1.y += a1.y;
            }
            *(float2*)&Cd[(size_t)r * 1024 + c] = v0;
            *(float2*)&Cd[(size_t)(r + 8) * 1024 + c] = v1;
        }
    }
}

// =====================================================================
// score[b,h,s] = (X[b,s,:] (* mul[b,:]) . Wa[:,h] + ba[h]) * 0.125 + mask[b,s]
// =====================================================================
__global__ __launch_bounds__(256)
void score_kernel(const float* __restrict__ X, const float* __restrict__ Wa,
                  const float* __restrict__ ba, const float* __restrict__ mask,
                  const float* __restrict__ mul, float* __restrict__ score)
{
    extern __shared__ float WaS[];  // [16][1024] transposed
    for (int idx = threadIdx.x; idx < 16 * 1024; idx += 256) {
        int d = idx >> 4, h = idx & 15;
        WaS[h * 1024 + d] = Wa[idx];
    }
    __syncthreads();

    int warp = threadIdx.x >> 5, lane = threadIdx.x & 31;
    int m = blockIdx.x * 8 + warp;
    int b = m >> 13, s = m & 8191;
    const float* xrow = X + (size_t)m * 1024;
    const float* mrow = mul ? (mul + b * 1024) : (const float*)0;

    float acc[16];
    #pragma unroll
    for (int h = 0; h < 16; h++) acc[h] = 0.f;

    #pragma unroll
    for (int it = 0; it < 8; it++) {
        int d = it * 128 + lane * 4;
        float4 x = *(const float4*)&xrow[d];
        if (mrow) {
            float4 mu = *(const float4*)&mrow[d];
            x.x *= mu.x; x.y *= mu.y; x.z *= mu.z; x.w *= mu.w;
        }
        #pragma unroll
        for (int h = 0; h < 16; h++) {
            float4 w = *(const float4*)&WaS[h * 1024 + d];
            acc[h] += x.x * w.x + x.y * w.y + x.z * w.z + x.w * w.w;
        }
    }
    #pragma unroll
    for (int off = 16; off > 0; off >>= 1)
        #pragma unroll
        for (int h = 0; h < 16; h++)
            acc[h] += __shfl_xor_sync(0xffffffffu, acc[h], off);

    if (lane == 0) {
        float mk = mask[(b << 13) + s];
        #pragma unroll
        for (int h = 0; h < 16; h++)
            score[(size_t)(b * 16 + h) * 8192 + s] = (acc[h] + ba[h]) * 0.125f + mk;
    }
}

// =====================================================================
// Softmax pooling, 3-phase for full-chip parallelism
// =====================================================================
__global__ void score_max_kernel(const float* __restrict__ sc, float* __restrict__ mx)
{
    __shared__ float red[256];
    int bh = blockIdx.x, tid = threadIdx.x;
    const float* p = sc + ((size_t)bh << 13);
    float m = -3.0e38f;
    for (int s = tid; s < 8192; s += 256) m = fmaxf(m, p[s]);
    red[tid] = m; __syncthreads();
    for (int st = 128; st > 0; st >>= 1) {
        if (tid < st) red[tid] = fmaxf(red[tid], red[tid + st]);
        __syncthreads();
    }
    if (tid == 0) mx[bh] = red[0];
}

__global__ __launch_bounds__(256)
void pool_partial_kernel(const float* __restrict__ score, const float* __restrict__ X,
                         const float* __restrict__ mxbuf, float* __restrict__ part)
{
    int bh = blockIdx.x, ch = blockIdx.y;
    int b = bh >> 4, h = bh & 15;
    const float* sc = score + ((size_t)bh << 13) + (ch << 10);
    int tid = threadIdx.x;
    float mx = mxbuf[bh];
    float acc[64];
    #pragma unroll
    for (int j = 0; j < 64; j++) acc[j] = 0.f;
    float sumw = 0.f;
    for (int s = tid; s < 1024; s += 256) {
        float w = expf(sc[s] - mx);
        sumw += w;
        const float4* xr = (const float4*)(X + ((size_t)((b << 13) + (ch << 10) + s)) * 1024 + h * 64);
        #pragma unroll
        for (int j = 0; j < 16; j++) {
            float4 v = xr[j];
            acc[4*j+0] += w*v.x; acc[4*j+1] += w*v.y;
            acc[4*j+2] += w*v.z; acc[4*j+3] += w*v.w;
        }
    }
    #pragma unroll
    for (int off = 16; off > 0; off >>= 1) {
        sumw += __shfl_xor_sync(0xffffffffu, sumw, off);
        #pragma unroll
        for (int j = 0; j < 64; j++)
            acc[j] += __shfl_xor_sync(0xffffffffu, acc[j], off);
    }
    __shared__ float sacc[8][64];
    __shared__ float ssum[8];
    int warp = tid >> 5, lane = tid & 31;
    if (lane == 0) ssum[warp] = sumw;
    #pragma unroll
    for (int j = 0; j < 64; j++)
        if ((j & 31) == lane) sacc[warp][j] = acc[j];
    __syncthreads();
    if (tid < 64) {
        float tot = 0.f, Z = 0.f;
        #pragma unroll
        for (int w = 0; w < 8; w++) { tot += sacc[w][tid]; Z += ssum[w]; }
        float* p = part + (size_t)(bh * 8 + ch) * 65;
        p[tid] = tot;
        if (tid == 0) p[64] = Z;
    }
}

__global__ void pool_combine_kernel(const float* __restrict__ part, const float* __restrict__ mul,
                                    float* __restrict__ pooled)
{
    int bh = blockIdx.x, tid = threadIdx.x;  // block 64
    int b = bh >> 4, h = bh & 15;
    float tot = 0.f, Z = 0.f;
    #pragma unroll
    for (int ch = 0; ch < 8; ch++) {
        const float* p = part + (size_t)(bh * 8 + ch) * 65;
        tot += p[tid]; Z += p[64];
    }
    float r = tot / Z;
    if (mul) r *= mul[b * 1024 + h * 64 + tid];
    pooled[b * 1024 + h * 64 + tid] = r;
}

// =====================================================================
extern "C" void kernel_launch(void* const* d_in, const int* in_sizes, int n_in,
                              void* d_out, int out_size)
{
    const float* hs   = (const float*)d_in[0];
    const float* mask = (const float*)d_in[1];
    const float* Wq   = (const float*)d_in[2];
    const float* bq   = (const float*)d_in[3];
    const float* Wqa  = (const float*)d_in[4];
    const float* bqa  = (const float*)d_in[5];
    const float* Wk   = (const float*)d_in[6];
    const float* bk   = (const float*)d_in[7];
    const float* Wka  = (const float*)d_in[8];
    const float* bka  = (const float*)d_in[9];
    const float* Wt   = (const float*)d_in[10];
    const float* bt   = (const float*)d_in[11];
    float* out = (float*)d_out;

    float *mq, *mk, *sco, *mx, *part, *pq, *pk;
    __nv_bfloat16 *Ah, *Al, *bqk_hi, *bqk_lo, *btp_hi, *btp_lo;
    cudaGetSymbolAddress((void**)&mq, g_mq);
    cudaGetSymbolAddress((void**)&mk, g_mk);
    cudaGetSymbolAddress((void**)&sco, g_score);
    cudaGetSymbolAddress((void**)&mx, g_mxv);
    cudaGetSymbolAddress((void**)&part, g_part);
    cudaGetSymbolAddress((void**)&pq, g_pq);
    cudaGetSymbolAddress((void**)&pk, g_pk);
    cudaGetSymbolAddress((void**)&Ah, g_Ah);
    cudaGetSymbolAddress((void**)&Al, g_Al);
    cudaGetSymbolAddress((void**)&bqk_hi, g_Bqk_hi);
    cudaGetSymbolAddress((void**)&bqk_lo, g_Bqk_lo);
    cudaGetSymbolAddress((void**)&btp_hi, g_Bt_hi);
    cudaGetSymbolAddress((void**)&btp_lo, g_Bt_lo);

    const int GSMEM = 122880;
    cudaFuncSetAttribute(hmma_gemm_kernel<true,  false>,
                         cudaFuncAttributeMaxDynamicSharedMemorySize, GSMEM);
    cudaFuncSetAttribute(hmma_gemm_kernel<false, true>,
                         cudaFuncAttributeMaxDynamicSharedMemorySize, GSMEM);
    cudaFuncSetAttribute(score_kernel, cudaFuncAttributeMaxDynamicSharedMemorySize, 65536);

    // ---- weight prep: transpose + bf16 hi/lo split
    dim3 wblk(32, 8), wgrd(32, 32);
    wprep_kernel<<<wgrd, wblk>>>(Wq, bqk_hi, bqk_lo);
    wprep_kernel<<<wgrd, wblk>>>(Wk, bqk_hi + 1024 * 1024, bqk_lo + 1024 * 1024);
    wprep_kernel<<<wgrd, wblk>>>(Wt, btp_hi, btp_lo);

    // ---- split hs into bf16 hi/lo
    asplit_kernel<false><<<32768, 256>>>(hs, nullptr, Ah, Al);

    // ---- fused mixed_q / mixed_k GEMM (N=2048 over [Wq|Wk])
    hmma_gemm_kernel<true, false><<<dim3(8, 256), 256, GSMEM>>>(
        Ah, Al, bqk_hi, bqk_lo, bq, bk, nullptr, mq, mk);

    // ---- q attention pooling
    score_kernel<<<4096, 256, 65536>>>(mq, Wqa, bqa, mask, nullptr, sco);
    score_max_kernel<<<64, 256>>>(sco, mx);
    pool_partial_kernel<<<dim3(64, 8), 256>>>(sco, mq, mx, part);
    pool_combine_kernel<<<64, 64>>>(part, nullptr, pq);

    // ---- k attention pooling (mixed_qk = mixed_k * pooled_q, never materialized)
    score_kernel<<<4096, 256, 65536>>>(mk, Wka, bka, mask, pq, sco);
    score_max_kernel<<<64, 256>>>(sco, mx);
    pool_partial_kernel<<<dim3(64, 8), 256>>>(sco, mk, mx, part);
    pool_combine_kernel<<<64, 64>>>(part, pq, pk);

    // ---- split (mixed_q * pooled_k) into bf16 hi/lo
    asplit_kernel<true><<<32768, 256>>>(mq, pk, Ah, Al);

    // ---- out = (mixed_q * pooled_k) @ Wt + bt + mixed_q
    hmma_gemm_kernel<false, true><<<dim3(4, 256), 256, GSMEM>>>(
        Ah, Al, btp_hi, btp_lo, bt, nullptr, mq, out, nullptr);
}

// round 11
// speedup vs baseline: 3.3868x; 1.2019x over previous
#include <cuda_runtime.h>
#include <cuda_bf16.h>
#include <math.h>
#include <stdint.h>

#define B_  4
#define S_  8192
#define D_  1024
#define H_  16
#define M_  (B_*S_)

// ---------------- scratch (device globals; no cudaMalloc) ----------------
__device__ float g_mq[(size_t)M_ * D_];                 // mixed_q  [B,S,D]
__device__ float g_mk[(size_t)M_ * D_];                 // mixed_k  [B,S,D]
__device__ __nv_bfloat16 g_Ah[(size_t)M_ * D_];         // A hi split
__device__ __nv_bfloat16 g_Al[(size_t)M_ * D_];         // A lo split
__device__ __nv_bfloat16 g_Bqk_hi[2048 * 1024];         // [n, k]  (Wq cols | Wk cols)
__device__ __nv_bfloat16 g_Bqk_lo[2048 * 1024];
__device__ __nv_bfloat16 g_Bt_hi[1024 * 1024];          // Wt^T
__device__ __nv_bfloat16 g_Bt_lo[1024 * 1024];
__device__ float g_score[B_ * H_ * S_];
__device__ float g_mxv[64];
__device__ float g_part[512 * 65];
__device__ float g_pq[B_ * D_];
__device__ float g_pk[B_ * D_];

// ---------------- helpers (sm_80-era PTX only: portable to sm_103) ----------------
__device__ __forceinline__ uint32_t smem_u32(const void* p) {
    uint32_t a;
    asm("{ .reg .u64 t; cvta.to.shared.u64 t, %1; cvt.u32.u64 %0, t; }" : "=r"(a) : "l"(p));
    return a;
}
__device__ __forceinline__ void cp16(uint32_t dst, const void* src) {
    asm volatile("cp.async.cg.shared.global [%0], [%1], 16;" :: "r"(dst), "l"(src));
}
__device__ __forceinline__ void ldsm4(uint32_t* r, uint32_t addr) {
    asm volatile("ldmatrix.sync.aligned.m8n8.x4.shared.b16 {%0,%1,%2,%3}, [%4];"
                 : "=r"(r[0]), "=r"(r[1]), "=r"(r[2]), "=r"(r[3]) : "r"(addr));
}
__device__ __forceinline__ void mma16816(float* d, const uint32_t* a, const uint32_t* b) {
    asm volatile("mma.sync.aligned.m16n8k16.row.col.f32.bf16.bf16.f32 "
                 "{%0,%1,%2,%3}, {%4,%5,%6,%7}, {%8,%9}, {%0,%1,%2,%3};"
                 : "+f"(d[0]), "+f"(d[1]), "+f"(d[2]), "+f"(d[3])
                 : "r"(a[0]), "r"(a[1]), "r"(a[2]), "r"(a[3]), "r"(b[0]), "r"(b[1]));
}
__device__ __forceinline__ uint32_t split_pack(float x, float y, uint32_t& lo) {
    __nv_bfloat16 hx = __float2bfloat16(x), hy = __float2bfloat16(y);
    __nv_bfloat16 lx = __float2bfloat16(x - __bfloat162float(hx));
    __nv_bfloat16 ly = __float2bfloat16(y - __bfloat162float(hy));
    lo = (uint32_t)__bfloat16_as_ushort(lx) | ((uint32_t)__bfloat16_as_ushort(ly) << 16);
    return (uint32_t)__bfloat16_as_ushort(hx) | ((uint32_t)__bfloat16_as_ushort(hy) << 16);
}

// =====================================================================
// Weight prep: out[n][k] = split(W[k][n]) as bf16 hi/lo (transpose+split)
// =====================================================================
__global__ void wprep_kernel(const float* __restrict__ W,
                             __nv_bfloat16* __restrict__ hi, __nv_bfloat16* __restrict__ lo)
{
    __shared__ float t[32][33];
    int n0 = blockIdx.x * 32, k0 = blockIdx.y * 32;
    int tx = threadIdx.x, ty = threadIdx.y;
    for (int i = ty; i < 32; i += 8)
        t[i][tx] = W[(size_t)(k0 + i) * 1024 + n0 + tx];
    __syncthreads();
    for (int i = ty; i < 32; i += 8) {
        float v = t[tx][i];  // W[k0+tx][n0+i]
        __nv_bfloat16 h = __float2bfloat16(v);
        __nv_bfloat16 l = __float2bfloat16(v - __bfloat162float(h));
        hi[(size_t)(n0 + i) * 1024 + k0 + tx] = h;
        lo[(size_t)(n0 + i) * 1024 + k0 + tx] = l;
    }
}

// =====================================================================
// A split: hi/lo bf16 of X (optionally scaled per (batch, d) by scaleK)
// =====================================================================
template<bool SCALE>
__global__ __launch_bounds__(256)
void asplit_kernel(const float* __restrict__ X, const float* __restrict__ scaleK,
                   __nv_bfloat16* __restrict__ hi, __nv_bfloat16* __restrict__ lo)
{
    size_t i = (size_t)blockIdx.x * 256 + threadIdx.x;   // float4 index
    float4 v = ((const float4*)X)[i];
    if (SCALE) {
        int d = (int)((i << 2) & 1023);
        int batch = (int)(i >> 21);                      // i/(8192*256)
        float4 sv = *(const float4*)&scaleK[batch * 1024 + d];
        v.x *= sv.x; v.y *= sv.y; v.z *= sv.z; v.w *= sv.w;
    }
    uint32_t l0, l1;
    uint32_t h0 = split_pack(v.x, v.y, l0);
    uint32_t h1 = split_pack(v.z, v.w, l1);
    ((uint2*)hi)[i] = make_uint2(h0, h1);
    ((uint2*)lo)[i] = make_uint2(l0, l1);
}

// =====================================================================
// HMMA bf16x3 GEMM:  C = Afp32 @ W + bias (+addC), via per-output-half
// pass counts: 3-pass = Ah*Bh + Al*Bh + Ah*Bl (rel err ~7e-6),
//              2-pass = Ah*Bh + Al*Bh         (rel err ~2e-3 on that output,
//                                              used only where diluted downstream).
// CTA tile 128x256, 8 warps (2M x 4N), warp tile 64x64, BK=32, 4-stage cp.async.
// SMEM/stage: A 128x80B (10240) + B 256x80B (20480) = 30720B; x4 = 122880B.
// =====================================================================
#define STAGE_BYTES 30720u
#define NSTAGE 4

__device__ __forceinline__ void issue_stage(
    int s, uint32_t smb, int brow, int bcol,
    const __nv_bfloat16* const* Aseg, const __nv_bfloat16* const* Bseg,
    int rr, int cc)
{
    const int st = s & (NSTAGE - 1);
    const int kg = s << 5;
    const int seg = kg >> 10;
    const int k0 = kg & 1023;
    const __nv_bfloat16* Ab = Aseg[seg];
    const __nv_bfloat16* Bb = Bseg[seg];
    uint32_t As = smb + (uint32_t)st * STAGE_BYTES;
    uint32_t Bs = As + 10240u;
    // A: 128 rows x 64B
    #pragma unroll
    for (int i = 0; i < 2; i++) {
        int r = rr + i * 64;
        cp16(As + (uint32_t)(r * 80 + cc * 2), Ab + (size_t)(brow + r) * 1024 + k0 + cc);
    }
    // B: 256 rows x 64B
    #pragma unroll
    for (int i = 0; i < 4; i++) {
        int r = rr + i * 64;
        cp16(Bs + (uint32_t)(r * 80 + cc * 2), Bb + (size_t)(bcol + r) * 1024 + k0 + cc);
    }
    asm volatile("cp.async.commit_group;" ::: "memory");
}

template<bool DUAL, bool ADD>
__global__ __launch_bounds__(256, 1)
void hmma_gemm_kernel(const __nv_bfloat16* __restrict__ Ah, const __nv_bfloat16* __restrict__ Al,
                      const __nv_bfloat16* __restrict__ Bh, const __nv_bfloat16* __restrict__ Bl,
                      const float* __restrict__ bias0, const float* __restrict__ bias1,
                      const float* __restrict__ addC,
                      float* __restrict__ C0, float* __restrict__ C1,
                      int npass0, int npass1)
{
    extern __shared__ char smraw[];
    const uint32_t smb = smem_u32(smraw);
    const int tid = threadIdx.x, lane = tid & 31, wid = tid >> 5;
    const int wr = wid & 1, wc = wid >> 1;
    const int brow = blockIdx.y * 128, bcol = blockIdx.x * 256;

    const __nv_bfloat16* Aseg[3] = {Ah, Al, Ah};
    const __nv_bfloat16* Bseg[3] = {Bh, Bh, Bl};

    // stages = 32 per pass; Wk/2-pass halves stop after Al*Bh
    const int nst = ((DUAL && bcol >= 1024) ? npass1 : npass0) << 5;

    float acc[4][8][4];
    #pragma unroll
    for (int mt = 0; mt < 4; mt++)
        #pragma unroll
        for (int nt = 0; nt < 8; nt++)
            #pragma unroll
            for (int j = 0; j < 4; j++) acc[mt][nt][j] = 0.f;

    const int rr = tid >> 2;         // 0..63
    const int cc = (tid & 3) * 8;    // element offset: 0,8,16,24

    issue_stage(0, smb, brow, bcol, Aseg, Bseg, rr, cc);
    issue_stage(1, smb, brow, bcol, Aseg, Bseg, rr, cc);
    issue_stage(2, smb, brow, bcol, Aseg, Bseg, rr, cc);

    const int am  = wr * 64 + (lane & 15);
    const int akh = (lane >> 4) * 8;
    const int g   = lane >> 3;
    const int bn  = wc * 64 + (lane & 7) + (g >> 1) * 8;
    const int bkh = (g & 1) * 8;

    for (int s = 0; s < nst; s++) {
        asm volatile("cp.async.wait_group 2;" ::: "memory");
        __syncthreads();
        if (s + 3 < nst) issue_stage(s + 3, smb, brow, bcol, Aseg, Bseg, rr, cc);
        else             asm volatile("cp.async.commit_group;" ::: "memory");

        uint32_t Asb = smb + (uint32_t)(s & (NSTAGE - 1)) * STAGE_BYTES;
        uint32_t Bsb = Asb + 10240u;
        #pragma unroll
        for (int kk = 0; kk < 2; kk++) {
            const int k = kk * 16;
            uint32_t a[4][4], b[4][4];
            #pragma unroll
            for (int mt = 0; mt < 4; mt++)
                ldsm4(a[mt], Asb + (uint32_t)((am + mt * 16) * 80 + (k + akh) * 2));
            #pragma unroll
            for (int bt = 0; bt < 4; bt++)
                ldsm4(b[bt], Bsb + (uint32_t)((bn + bt * 16) * 80 + (k + bkh) * 2));
            #pragma unroll
            for (int mt = 0; mt < 4; mt++)
                #pragma unroll
                for (int nt = 0; nt < 8; nt++)
                    mma16816(acc[mt][nt], a[mt], &b[nt >> 1][(nt & 1) * 2]);
        }
    }

    // ---- epilogue
    const float* bias = bias0;
    float* Cd = C0;
    int ceff = bcol;
    if (DUAL && bcol >= 1024) { bias = bias1; Cd = C1; ceff = bcol - 1024; }

    #pragma unroll
    for (int mt = 0; mt < 4; mt++) {
        const int r = brow + wr * 64 + mt * 16 + (lane >> 2);
        #pragma unroll
        for (int nt = 0; nt < 8; nt++) {
            const int c = ceff + wc * 64 + nt * 8 + (lane & 3) * 2;
            float2 bi = *(const float2*)&bias[c];
            float2 v0 = make_float2(acc[mt][nt][0] + bi.x, acc[mt][nt][1] + bi.y);
            float2 v1 = make_float2(acc[mt][nt][2] + bi.x, acc[mt][nt][3] + bi.y);
            if (ADD) {
                float2 a0 = *(const float2*)&addC[(size_t)r * 1024 + c];
                float2 a1 = *(const float2*)&addC[(size_t)(r + 8) * 1024 + c];
                v0.x += a0.x; v0.y += a0.y; v1.x += a1.x; v1.y += a1.y;
            }
            *(float2*)&Cd[(size_t)r * 1024 + c] = v0;
            *(float2*)&Cd[(size_t)(r + 8) * 1024 + c] = v1;
        }
    }
}

// =====================================================================
// score[b,h,s] = (X[b,s,:] (* mul[b,:]) . Wa[:,h] + ba[h]) * 0.125 + mask[b,s]
// =====================================================================
__global__ __launch_bounds__(256)
void score_kernel(const float* __restrict__ X, const float* __restrict__ Wa,
                  const float* __restrict__ ba, const float* __restrict__ mask,
                  const float* __restrict__ mul, float* __restrict__ score)
{
    extern __shared__ float WaS[];  // [16][1024] transposed
    for (int idx = threadIdx.x; idx < 16 * 1024; idx += 256) {
        int d = idx >> 4, h = idx & 15;
        WaS[h * 1024 + d] = Wa[idx];
    }
    __syncthreads();

    int warp = threadIdx.x >> 5, lane = threadIdx.x & 31;
    int m = blockIdx.x * 8 + warp;
    int b = m >> 13, s = m & 8191;
    const float* xrow = X + (size_t)m * 1024;
    const float* mrow = mul ? (mul + b * 1024) : (const float*)0;

    float acc[16];
    #pragma unroll
    for (int h = 0; h < 16; h++) acc[h] = 0.f;

    #pragma unroll
    for (int it = 0; it < 8; it++) {
        int d = it * 128 + lane * 4;
        float4 x = *(const float4*)&xrow[d];
        if (mrow) {
            float4 mu = *(const float4*)&mrow[d];
            x.x *= mu.x; x.y *= mu.y; x.z *= mu.z; x.w *= mu.w;
        }
        #pragma unroll
        for (int h = 0; h < 16; h++) {
            float4 w = *(const float4*)&WaS[h * 1024 + d];
            acc[h] += x.x * w.x + x.y * w.y + x.z * w.z + x.w * w.w;
        }
    }
    #pragma unroll
    for (int off = 16; off > 0; off >>= 1)
        #pragma unroll
        for (int h = 0; h < 16; h++)
            acc[h] += __shfl_xor_sync(0xffffffffu, acc[h], off);

    if (lane == 0) {
        float mk = mask[(b << 13) + s];
        #pragma unroll
        for (int h = 0; h < 16; h++)
            score[(size_t)(b * 16 + h) * 8192 + s] = (acc[h] + ba[h]) * 0.125f + mk;
    }
}

// =====================================================================
// Softmax pooling, 3-phase for full-chip parallelism
// =====================================================================
__global__ void score_max_kernel(const float* __restrict__ sc, float* __restrict__ mx)
{
    __shared__ float red[256];
    int bh = blockIdx.x, tid = threadIdx.x;
    const float* p = sc + ((size_t)bh << 13);
    float m = -3.0e38f;
    for (int s = tid; s < 8192; s += 256) m = fmaxf(m, p[s]);
    red[tid] = m; __syncthreads();
    for (int st = 128; st > 0; st >>= 1) {
        if (tid < st) red[tid] = fmaxf(red[tid], red[tid + st]);
        __syncthreads();
    }
    if (tid == 0) mx[bh] = red[0];
}

__global__ __launch_bounds__(256)
void pool_partial_kernel(const float* __restrict__ score, const float* __restrict__ X,
                         const float* __restrict__ mxbuf, float* __restrict__ part)
{
    int bh = blockIdx.x, ch = blockIdx.y;
    int b = bh >> 4, h = bh & 15;
    const float* sc = score + ((size_t)bh << 13) + (ch << 10);
    int tid = threadIdx.x;
    float mx = mxbuf[bh];
    float acc[64];
    #pragma unroll
    for (int j = 0; j < 64; j++) acc[j] = 0.f;
    float sumw = 0.f;
    for (int s = tid; s < 1024; s += 256) {
        float w = expf(sc[s] - mx);
        sumw += w;
        const float4* xr = (const float4*)(X + ((size_t)((b << 13) + (ch << 10) + s)) * 1024 + h * 64);
        #pragma unroll
        for (int j = 0; j < 16; j++) {
            float4 v = xr[j];
            acc[4*j+0] += w*v.x; acc[4*j+1] += w*v.y;
            acc[4*j+2] += w*v.z; acc[4*j+3] += w*v.w;
        }
    }
    #pragma unroll
    for (int off = 16; off > 0; off >>= 1) {
        sumw += __shfl_xor_sync(0xffffffffu, sumw, off);
        #pragma unroll
        for (int j = 0; j < 64; j++)
            acc[j] += __shfl_xor_sync(0xffffffffu, acc[j], off);
    }
    __shared__ float sacc[8][64];
    __shared__ float ssum[8];
    int warp = tid >> 5, lane = tid & 31;
    if (lane == 0) ssum[warp] = sumw;
    #pragma unroll
    for (int j = 0; j < 64; j++)
        if ((j & 31) == lane) sacc[warp][j] = acc[j];
    __syncthreads();
    if (tid < 64) {
        float tot = 0.f, Z = 0.f;
        #pragma unroll
        for (int w = 0; w < 8; w++) { tot += sacc[w][tid]; Z += ssum[w]; }
        float* p = part + (size_t)(bh * 8 + ch) * 65;
        p[tid] = tot;
        if (tid == 0) p[64] = Z;
    }
}

__global__ void pool_combine_kernel(const float* __restrict__ part, const float* __restrict__ mul,
                                    float* __restrict__ pooled)
{
    int bh = blockIdx.x, tid = threadIdx.x;  // block 64
    int b = bh >> 4, h = bh & 15;
    float tot = 0.f, Z = 0.f;
    #pragma unroll
    for (int ch = 0; ch < 8; ch++) {
        const float* p = part + (size_t)(bh * 8 + ch) * 65;
        tot += p[tid]; Z += p[64];
    }
    float r = tot / Z;
    if (mul) r *= mul[b * 1024 + h * 64 + tid];
    pooled[b * 1024 + h * 64 + tid] = r;
}

// =====================================================================
extern "C" void kernel_launch(void* const* d_in, const int* in_sizes, int n_in,
                              void* d_out, int out_size)
{
    const float* hs   = (const float*)d_in[0];
    const float* mask = (const float*)d_in[1];
    const float* Wq   = (const float*)d_in[2];
    const float* bq   = (const float*)d_in[3];
    const float* Wqa  = (const float*)d_in[4];
    const float* bqa  = (const float*)d_in[5];
    const float* Wk   = (const float*)d_in[6];
    const float* bk   = (const float*)d_in[7];
    const float* Wka  = (const float*)d_in[8];
    const float* bka  = (const float*)d_in[9];
    const float* Wt   = (const float*)d_in[10];
    const float* bt   = (const float*)d_in[11];
    float* out = (float*)d_out;

    float *mq, *mk, *sco, *mx, *part, *pq, *pk;
    __nv_bfloat16 *Ah, *Al, *bqk_hi, *bqk_lo, *btp_hi, *btp_lo;
    cudaGetSymbolAddress((void**)&mq, g_mq);
    cudaGetSymbolAddress((void**)&mk, g_mk);
    cudaGetSymbolAddress((void**)&sco, g_score);
    cudaGetSymbolAddress((void**)&mx, g_mxv);
    cudaGetSymbolAddress((void**)&part, g_part);
    cudaGetSymbolAddress((void**)&pq, g_pq);
    cudaGetSymbolAddress((void**)&pk, g_pk);
    cudaGetSymbolAddress((void**)&Ah, g_Ah);
    cudaGetSymbolAddress((void**)&Al, g_Al);
    cudaGetSymbolAddress((void**)&bqk_hi, g_Bqk_hi);
    cudaGetSymbolAddress((void**)&bqk_lo, g_Bqk_lo);
    cudaGetSymbolAddress((void**)&btp_hi, g_Bt_hi);
    cudaGetSymbolAddress((void**)&btp_lo, g_Bt_lo);

    const int GSMEM = 122880;
    cudaFuncSetAttribute(hmma_gemm_kernel<true,  false>,
                         cudaFuncAttributeMaxDynamicSharedMemorySize, GSMEM);
    cudaFuncSetAttribute(hmma_gemm_kernel<false, true>,
                         cudaFuncAttributeMaxDynamicSharedMemorySize, GSMEM);
    cudaFuncSetAttribute(score_kernel, cudaFuncAttributeMaxDynamicSharedMemorySize, 65536);

    // ---- weight prep: transpose + bf16 hi/lo split
    dim3 wblk(32, 8), wgrd(32, 32);
    wprep_kernel<<<wgrd, wblk>>>(Wq, bqk_hi, bqk_lo);
    wprep_kernel<<<wgrd, wblk>>>(Wk, bqk_hi + 1024 * 1024, bqk_lo + 1024 * 1024);
    wprep_kernel<<<wgrd, wblk>>>(Wt, btp_hi, btp_lo);

    // ---- split hs into bf16 hi/lo
    asplit_kernel<false><<<32768, 256>>>(hs, nullptr, Ah, Al);

    // ---- fused mixed_q / mixed_k GEMM (N=2048 over [Wq|Wk])
    // Wq half: 3-pass (full precision, feeds output residual directly).
    // Wk half: 2-pass (error diluted ~0.26x through pooling chain).
    hmma_gemm_kernel<true, false><<<dim3(8, 256), 256, GSMEM>>>(
        Ah, Al, bqk_hi, bqk_lo, bq, bk, nullptr, mq, mk, 3, 2);

    // ---- q attention pooling
    score_kernel<<<4096, 256, 65536>>>(mq, Wqa, bqa, mask, nullptr, sco);
    score_max_kernel<<<64, 256>>>(sco, mx);
    pool_partial_kernel<<<dim3(64, 8), 256>>>(sco, mq, mx, part);
    pool_combine_kernel<<<64, 64>>>(part, nullptr, pq);

    // ---- k attention pooling (mixed_qk = mixed_k * pooled_q, never materialized)
    score_kernel<<<4096, 256, 65536>>>(mk, Wka, bka, mask, pq, sco);
    score_max_kernel<<<64, 256>>>(sco, mx);
    pool_partial_kernel<<<dim3(64, 8), 256>>>(sco, mk, mx, part);
    pool_combine_kernel<<<64, 64>>>(part, pq, pk);

    // ---- split (mixed_q * pooled_k) into bf16 hi/lo
    asplit_kernel<true><<<32768, 256>>>(mq, pk, Ah, Al);

    // ---- out = (mixed_q * pooled_k) @ Wt + bt + mixed_q  (2-pass: term is 0.26x of out)
    hmma_gemm_kernel<false, true><<<dim3(4, 256), 256, GSMEM>>>(
        Ah, Al, btp_hi, btp_lo, bt, nullptr, mq, out, nullptr, 2, 2);
}

// round 12
// speedup vs baseline: 4.8907x; 1.4440x over previous
#include <cuda_runtime.h>
#include <cuda_fp16.h>
#include <math.h>
#include <stdint.h>

#define B_  4
#define S_  8192
#define D_  1024
#define H_  16
#define M_  (B_*S_)

// ---------------- scratch (device globals; no cudaMalloc) ----------------
__device__ float g_mq[(size_t)M_ * D_];                 // mixed_q  [B,S,D]
__device__ float g_mk[(size_t)M_ * D_];                 // mixed_k  [B,S,D]
__device__ __half g_Ah[(size_t)M_ * D_];                // A hi split (fp16)
__device__ __half g_Al[(size_t)M_ * D_];                // A lo split (fp16)
__device__ __half g_Bqk[2048 * 1024];                   // [n, k] fp16 (Wq cols | Wk cols)
__device__ __half g_Bt[1024 * 1024];                    // Wt^T fp16
__device__ float g_score[B_ * H_ * S_];
__device__ float g_mxv[64];
__device__ float g_part[512 * 65];
__device__ float g_pq[B_ * D_];
__device__ float g_pk[B_ * D_];

// ---------------- helpers (sm_80-era PTX only: portable to sm_103) ----------------
__device__ __forceinline__ uint32_t smem_u32(const void* p) {
    uint32_t a;
    asm("{ .reg .u64 t; cvta.to.shared.u64 t, %1; cvt.u32.u64 %0, t; }" : "=r"(a) : "l"(p));
    return a;
}
__device__ __forceinline__ void cp16(uint32_t dst, const void* src) {
    asm volatile("cp.async.cg.shared.global [%0], [%1], 16;" :: "r"(dst), "l"(src));
}
__device__ __forceinline__ void ldsm4(uint32_t* r, uint32_t addr) {
    asm volatile("ldmatrix.sync.aligned.m8n8.x4.shared.b16 {%0,%1,%2,%3}, [%4];"
                 : "=r"(r[0]), "=r"(r[1]), "=r"(r[2]), "=r"(r[3]) : "r"(addr));
}
__device__ __forceinline__ void mma16816(float* d, const uint32_t* a, const uint32_t* b) {
    asm volatile("mma.sync.aligned.m16n8k16.row.col.f32.f16.f16.f32 "
                 "{%0,%1,%2,%3}, {%4,%5,%6,%7}, {%8,%9}, {%0,%1,%2,%3};"
                 : "+f"(d[0]), "+f"(d[1]), "+f"(d[2]), "+f"(d[3])
                 : "r"(a[0]), "r"(a[1]), "r"(a[2]), "r"(a[3]), "r"(b[0]), "r"(b[1]));
}
__device__ __forceinline__ uint32_t split_pack(float x, float y, uint32_t& lo) {
    __half hx = __float2half(x), hy = __float2half(y);
    __half lx = __float2half(x - __half2float(hx));
    __half ly = __float2half(y - __half2float(hy));
    lo = (uint32_t)__half_as_ushort(lx) | ((uint32_t)__half_as_ushort(ly) << 16);
    return (uint32_t)__half_as_ushort(hx) | ((uint32_t)__half_as_ushort(hy) << 16);
}

// =====================================================================
// Weight prep: out[n][k] = fp16(W[k][n])  (transpose + fp16 round)
// =====================================================================
__global__ void wprep_kernel(const float* __restrict__ W, __half* __restrict__ hi)
{
    __shared__ float t[32][33];
    int n0 = blockIdx.x * 32, k0 = blockIdx.y * 32;
    int tx = threadIdx.x, ty = threadIdx.y;
    for (int i = ty; i < 32; i += 8)
        t[i][tx] = W[(size_t)(k0 + i) * 1024 + n0 + tx];
    __syncthreads();
    for (int i = ty; i < 32; i += 8)
        hi[(size_t)(n0 + i) * 1024 + k0 + tx] = __float2half(t[tx][i]);
}

// =====================================================================
// A split: hi(/lo) fp16 of X (optionally scaled per (batch, d) by scaleK)
// =====================================================================
template<bool SCALE, bool WLO>
__global__ __launch_bounds__(256)
void asplit_kernel(const float* __restrict__ X, const float* __restrict__ scaleK,
                   __half* __restrict__ hi, __half* __restrict__ lo)
{
    size_t i = (size_t)blockIdx.x * 256 + threadIdx.x;   // float4 index
    float4 v = ((const float4*)X)[i];
    if (SCALE) {
        int d = (int)((i << 2) & 1023);
        int batch = (int)(i >> 21);                      // i/(8192*256)
        float4 sv = *(const float4*)&scaleK[batch * 1024 + d];
        v.x *= sv.x; v.y *= sv.y; v.z *= sv.z; v.w *= sv.w;
    }
    uint32_t l0, l1;
    uint32_t h0 = split_pack(v.x, v.y, l0);
    uint32_t h1 = split_pack(v.z, v.w, l1);
    ((uint2*)hi)[i] = make_uint2(h0, h1);
    if (WLO) ((uint2*)lo)[i] = make_uint2(l0, l1);
}

// =====================================================================
// HMMA fp16 GEMM with per-output-half pass counts:
//   2-pass = Ah*B + Al*B  (A exact to 2^-22; err = B fp16 rounding ~2.8e-4)
//   1-pass = Ah*B         (err ~4e-4; used where diluted downstream)
// CTA tile 128x256, 8 warps (2M x 4N), warp tile 64x64, BK=32, 4-stage cp.async.
// SMEM/stage: A 128x80B (10240) + B 256x80B (20480) = 30720B; x4 = 122880B.
// =====================================================================
#define STAGE_BYTES 30720u
#define NSTAGE 4

__device__ __forceinline__ void issue_stage(
    int s, uint32_t smb, int brow, int bcol,
    const __half* const* Aseg, const __half* Bb,
    int rr, int cc)
{
    const int st = s & (NSTAGE - 1);
    const int kg = s << 5;
    const int seg = kg >> 10;
    const int k0 = kg & 1023;
    const __half* Ab = Aseg[seg];
    uint32_t As = smb + (uint32_t)st * STAGE_BYTES;
    uint32_t Bs = As + 10240u;
    // A: 128 rows x 64B
    #pragma unroll
    for (int i = 0; i < 2; i++) {
        int r = rr + i * 64;
        cp16(As + (uint32_t)(r * 80 + cc * 2), Ab + (size_t)(brow + r) * 1024 + k0 + cc);
    }
    // B: 256 rows x 64B
    #pragma unroll
    for (int i = 0; i < 4; i++) {
        int r = rr + i * 64;
        cp16(Bs + (uint32_t)(r * 80 + cc * 2), Bb + (size_t)(bcol + r) * 1024 + k0 + cc);
    }
    asm volatile("cp.async.commit_group;" ::: "memory");
}

template<bool DUAL, bool ADD>
__global__ __launch_bounds__(256, 1)
void hmma_gemm_kernel(const __half* __restrict__ Ah, const __half* __restrict__ Al,
                      const __half* __restrict__ B,
                      const float* __restrict__ bias0, const float* __restrict__ bias1,
                      const float* __restrict__ addC,
                      float* __restrict__ C0, float* __restrict__ C1,
                      int npass0, int npass1)
{
    extern __shared__ char smraw[];
    const uint32_t smb = smem_u32(smraw);
    const int tid = threadIdx.x, lane = tid & 31, wid = tid >> 5;
    const int wr = wid & 1, wc = wid >> 1;
    const int brow = blockIdx.y * 128, bcol = blockIdx.x * 256;

    const __half* Aseg[2] = {Ah, Al};

    // stages = 32 per pass
    const int nst = ((DUAL && bcol >= 1024) ? npass1 : npass0) << 5;

    float acc[4][8][4];
    #pragma unroll
    for (int mt = 0; mt < 4; mt++)
        #pragma unroll
        for (int nt = 0; nt < 8; nt++)
            #pragma unroll
            for (int j = 0; j < 4; j++) acc[mt][nt][j] = 0.f;

    const int rr = tid >> 2;         // 0..63
    const int cc = (tid & 3) * 8;    // element offset: 0,8,16,24

    issue_stage(0, smb, brow, bcol, Aseg, B, rr, cc);
    issue_stage(1, smb, brow, bcol, Aseg, B, rr, cc);
    issue_stage(2, smb, brow, bcol, Aseg, B, rr, cc);

    const int am  = wr * 64 + (lane & 15);
    const int akh = (lane >> 4) * 8;
    const int g   = lane >> 3;
    const int bn  = wc * 64 + (lane & 7) + (g >> 1) * 8;
    const int bkh = (g & 1) * 8;

    for (int s = 0; s < nst; s++) {
        asm volatile("cp.async.wait_group 2;" ::: "memory");
        __syncthreads();
        if (s + 3 < nst) issue_stage(s + 3, smb, brow, bcol, Aseg, B, rr, cc);
        else             asm volatile("cp.async.commit_group;" ::: "memory");

        uint32_t Asb = smb + (uint32_t)(s & (NSTAGE - 1)) * STAGE_BYTES;
        uint32_t Bsb = Asb + 10240u;
        #pragma unroll
        for (int kk = 0; kk < 2; kk++) {
            const int k = kk * 16;
            uint32_t a[4][4], b[4][4];
            #pragma unroll
            for (int mt = 0; mt < 4; mt++)
                ldsm4(a[mt], Asb + (uint32_t)((am + mt * 16) * 80 + (k + akh) * 2));
            #pragma unroll
            for (int bt = 0; bt < 4; bt++)
                ldsm4(b[bt], Bsb + (uint32_t)((bn + bt * 16) * 80 + (k + bkh) * 2));
            #pragma unroll
            for (int mt = 0; mt < 4; mt++)
                #pragma unroll
                for (int nt = 0; nt < 8; nt++)
                    mma16816(acc[mt][nt], a[mt], &b[nt >> 1][(nt & 1) * 2]);
        }
    }

    // ---- epilogue
    const float* bias = bias0;
    float* Cd = C0;
    int ceff = bcol;
    if (DUAL && bcol >= 1024) { bias = bias1; Cd = C1; ceff = bcol - 1024; }

    #pragma unroll
    for (int mt = 0; mt < 4; mt++) {
        const int r = brow + wr * 64 + mt * 16 + (lane >> 2);
        #pragma unroll
        for (int nt = 0; nt < 8; nt++) {
            const int c = ceff + wc * 64 + nt * 8 + (lane & 3) * 2;
            float2 bi = *(const float2*)&bias[c];
            float2 v0 = make_float2(acc[mt][nt][0] + bi.x, acc[mt][nt][1] + bi.y);
            float2 v1 = make_float2(acc[mt][nt][2] + bi.x, acc[mt][nt][3] + bi.y);
            if (ADD) {
                float2 a0 = *(const float2*)&addC[(size_t)r * 1024 + c];
                float2 a1 = *(const float2*)&addC[(size_t)(r + 8) * 1024 + c];
                v0.x += a0.x; v0.y += a0.y; v1.x += a1.x; v1.y += a1.y;
            }
            *(float2*)&Cd[(size_t)r * 1024 + c] = v0;
            *(float2*)&Cd[(size_t)(r + 8) * 1024 + c] = v1;
        }
    }
}

// =====================================================================
// score[b,h,s] = (X[b,s,:] (* mul[b,:]) . Wa[:,h] + ba[h]) * 0.125 + mask[b,s]
// =====================================================================
__global__ __launch_bounds__(256)
void score_kernel(const float* __restrict__ X, const float* __restrict__ Wa,
                  const float* __restrict__ ba, const float* __restrict__ mask,
                  const float* __restrict__ mul, float* __restrict__ score)
{
    extern __shared__ float WaS[];  // [16][1024] transposed
    for (int idx = threadIdx.x; idx < 16 * 1024; idx += 256) {
        int d = idx >> 4, h = idx & 15;
        WaS[h * 1024 + d] = Wa[idx];
    }
    __syncthreads();

    int warp = threadIdx.x >> 5, lane = threadIdx.x & 31;
    int m = blockIdx.x * 8 + warp;
    int b = m >> 13, s = m & 8191;
    const float* xrow = X + (size_t)m * 1024;
    const float* mrow = mul ? (mul + b * 1024) : (const float*)0;

    float acc[16];
    #pragma unroll
    for (int h = 0; h < 16; h++) acc[h] = 0.f;

    #pragma unroll
    for (int it = 0; it < 8; it++) {
        int d = it * 128 + lane * 4;
        float4 x = *(const float4*)&xrow[d];
        if (mrow) {
            float4 mu = *(const float4*)&mrow[d];
            x.x *= mu.x; x.y *= mu.y; x.z *= mu.z; x.w *= mu.w;
        }
        #pragma unroll
        for (int h = 0; h < 16; h++) {
            float4 w = *(const float4*)&WaS[h * 1024 + d];
            acc[h] += x.x * w.x + x.y * w.y + x.z * w.z + x.w * w.w;
        }
    }
    #pragma unroll
    for (int off = 16; off > 0; off >>= 1)
        #pragma unroll
        for (int h = 0; h < 16; h++)
            acc[h] += __shfl_xor_sync(0xffffffffu, acc[h], off);

    if (lane == 0) {
        float mk = mask[(b << 13) + s];
        #pragma unroll
        for (int h = 0; h < 16; h++)
            score[(size_t)(b * 16 + h) * 8192 + s] = (acc[h] + ba[h]) * 0.125f + mk;
    }
}

// =====================================================================
// Softmax pooling, 3-phase for full-chip parallelism
// =====================================================================
__global__ void score_max_kernel(const float* __restrict__ sc, float* __restrict__ mx)
{
    __shared__ float red[256];
    int bh = blockIdx.x, tid = threadIdx.x;
    const float* p = sc + ((size_t)bh << 13);
    float m = -3.0e38f;
    for (int s = tid; s < 8192; s += 256) m = fmaxf(m, p[s]);
    red[tid] = m; __syncthreads();
    for (int st = 128; st > 0; st >>= 1) {
        if (tid < st) red[tid] = fmaxf(red[tid], red[tid + st]);
        __syncthreads();
    }
    if (tid == 0) mx[bh] = red[0];
}

__global__ __launch_bounds__(256)
void pool_partial_kernel(const float* __restrict__ score, const float* __restrict__ X,
                         const float* __restrict__ mxbuf, float* __restrict__ part)
{
    int bh = blockIdx.x, ch = blockIdx.y;
    int b = bh >> 4, h = bh & 15;
    const float* sc = score + ((size_t)bh << 13) + (ch << 10);
    int tid = threadIdx.x;
    float mx = mxbuf[bh];
    float acc[64];
    #pragma unroll
    for (int j = 0; j < 64; j++) acc[j] = 0.f;
    float sumw = 0.f;
    for (int s = tid; s < 1024; s += 256) {
        float w = expf(sc[s] - mx);
        sumw += w;
        const float4* xr = (const float4*)(X + ((size_t)((b << 13) + (ch << 10) + s)) * 1024 + h * 64);
        #pragma unroll
        for (int j = 0; j < 16; j++) {
            float4 v = xr[j];
            acc[4*j+0] += w*v.x; acc[4*j+1] += w*v.y;
            acc[4*j+2] += w*v.z; acc[4*j+3] += w*v.w;
        }
    }
    #pragma unroll
    for (int off = 16; off > 0; off >>= 1) {
        sumw += __shfl_xor_sync(0xffffffffu, sumw, off);
        #pragma unroll
        for (int j = 0; j < 64; j++)
            acc[j] += __shfl_xor_sync(0xffffffffu, acc[j], off);
    }
    __shared__ float sacc[8][64];
    __shared__ float ssum[8];
    int warp = tid >> 5, lane = tid & 31;
    if (lane == 0) ssum[warp] = sumw;
    #pragma unroll
    for (int j = 0; j < 64; j++)
        if ((j & 31) == lane) sacc[warp][j] = acc[j];
    __syncthreads();
    if (tid < 64) {
        float tot = 0.f, Z = 0.f;
        #pragma unroll
        for (int w = 0; w < 8; w++) { tot += sacc[w][tid]; Z += ssum[w]; }
        float* p = part + (size_t)(bh * 8 + ch) * 65;
        p[tid] = tot;
        if (tid == 0) p[64] = Z;
    }
}

__global__ void pool_combine_kernel(const float* __restrict__ part, const float* __restrict__ mul,
                                    float* __restrict__ pooled)
{
    int bh = blockIdx.x, tid = threadIdx.x;  // block 64
    int b = bh >> 4, h = bh & 15;
    float tot = 0.f, Z = 0.f;
    #pragma unroll
    for (int ch = 0; ch < 8; ch++) {
        const float* p = part + (size_t)(bh * 8 + ch) * 65;
        tot += p[tid]; Z += p[64];
    }
    float r = tot / Z;
    if (mul) r *= mul[b * 1024 + h * 64 + tid];
    pooled[b * 1024 + h * 64 + tid] = r;
}

// =====================================================================
extern "C" void kernel_launch(void* const* d_in, const int* in_sizes, int n_in,
                              void* d_out, int out_size)
{
    const float* hs   = (const float*)d_in[0];
    const float* mask = (const float*)d_in[1];
    const float* Wq   = (const float*)d_in[2];
    const float* bq   = (const float*)d_in[3];
    const float* Wqa  = (const float*)d_in[4];
    const float* bqa  = (const float*)d_in[5];
    const float* Wk   = (const float*)d_in[6];
    const float* bk   = (const float*)d_in[7];
    const float* Wka  = (const float*)d_in[8];
    const float* bka  = (const float*)d_in[9];
    const float* Wt   = (const float*)d_in[10];
    const float* bt   = (const float*)d_in[11];
    float* out = (float*)d_out;

    float *mq, *mk, *sco, *mx, *part, *pq, *pk;
    __half *Ah, *Al, *bqk, *btp;
    cudaGetSymbolAddress((void**)&mq, g_mq);
    cudaGetSymbolAddress((void**)&mk, g_mk);
    cudaGetSymbolAddress((void**)&sco, g_score);
    cudaGetSymbolAddress((void**)&mx, g_mxv);
    cudaGetSymbolAddress((void**)&part, g_part);
    cudaGetSymbolAddress((void**)&pq, g_pq);
    cudaGetSymbolAddress((void**)&pk, g_pk);
    cudaGetSymbolAddress((void**)&Ah, g_Ah);
    cudaGetSymbolAddress((void**)&Al, g_Al);
    cudaGetSymbolAddress((void**)&bqk, g_Bqk);
    cudaGetSymbolAddress((void**)&btp, g_Bt);

    const int GSMEM = 122880;
    cudaFuncSetAttribute(hmma_gemm_kernel<true,  false>,
                         cudaFuncAttributeMaxDynamicSharedMemorySize, GSMEM);
    cudaFuncSetAttribute(hmma_gemm_kernel<false, true>,
                         cudaFuncAttributeMaxDynamicSharedMemorySize, GSMEM);
    cudaFuncSetAttribute(score_kernel, cudaFuncAttributeMaxDynamicSharedMemorySize, 65536);

    // ---- weight prep: transpose + fp16 round
    dim3 wblk(32, 8), wgrd(32, 32);
    wprep_kernel<<<wgrd, wblk>>>(Wq, bqk);
    wprep_kernel<<<wgrd, wblk>>>(Wk, bqk + 1024 * 1024);
    wprep_kernel<<<wgrd, wblk>>>(Wt, btp);

    // ---- split hs into fp16 hi/lo
    asplit_kernel<false, true><<<32768, 256>>>(hs, nullptr, Ah, Al);

    // ---- fused mixed_q / mixed_k GEMM (N=2048 over [Wq|Wk])
    // Wq half: 2-pass (A exact; err = Wq fp16 rounding ~2.8e-4, direct in out).
    // Wk half: 1-pass (err ~4e-4, diluted through pooling chain).
    hmma_gemm_kernel<true, false><<<dim3(8, 256), 256, GSMEM>>>(
        Ah, Al, bqk, bq, bk, nullptr, mq, mk, 2, 1);

    // ---- q attention pooling
    score_kernel<<<4096, 256, 65536>>>(mq, Wqa, bqa, mask, nullptr, sco);
    score_max_kernel<<<64, 256>>>(sco, mx);
    pool_partial_kernel<<<dim3(64, 8), 256>>>(sco, mq, mx, part);
    pool_combine_kernel<<<64, 64>>>(part, nullptr, pq);

    // ---- k attention pooling (mixed_qk = mixed_k * pooled_q, never materialized)
    score_kernel<<<4096, 256, 65536>>>(mk, Wka, bka, mask, pq, sco);
    score_max_kernel<<<64, 256>>>(sco, mx);
    pool_partial_kernel<<<dim3(64, 8), 256>>>(sco, mk, mx, part);
    pool_combine_kernel<<<64, 64>>>(part, pq, pk);

    // ---- split (mixed_q * pooled_k) into fp16 (hi only; 1-pass GEMM3)
    asplit_kernel<true, false><<<32768, 256>>>(mq, pk, Ah, nullptr);

    // ---- out = (mixed_q * pooled_k) @ Wt + bt + mixed_q  (1-pass; term ~0.26x of out)
    hmma_gemm_kernel<false, true><<<dim3(4, 256), 256, GSMEM>>>(
        Ah, Al, btp, bt, nullptr, mq, out, nullptr, 1, 1);
}

// round 13
// speedup vs baseline: 6.6415x; 1.3580x over previous
#include <cuda_runtime.h>
#include <cuda_fp16.h>
#include <math.h>
#include <stdint.h>

#define B_  4
#define S_  8192
#define D_  1024
#define H_  16
#define M_  (B_*S_)

// ---------------- scratch (device globals; no cudaMalloc) ----------------
__device__ float g_mq[(size_t)M_ * D_];                 // mixed_q  [B,S,D]
__device__ float g_mk[(size_t)M_ * D_];                 // mixed_k  [B,S,D]
__device__ __half g_Ah[(size_t)M_ * D_];                // A fp16
__device__ __half g_Bqk[2048 * 1024];                   // [n, k] fp16 (Wq cols | Wk cols)
__device__ __half g_Bt[1024 * 1024];                    // Wt^T fp16
__device__ float g_score[B_ * H_ * S_];
__device__ float g_part[512 * 65];
__device__ float g_pq[B_ * D_];
__device__ float g_pk[B_ * D_];

// ---------------- helpers (sm_80-era PTX only: portable to sm_103) ----------------
__device__ __forceinline__ uint32_t smem_u32(const void* p) {
    uint32_t a;
    asm("{ .reg .u64 t; cvta.to.shared.u64 t, %1; cvt.u32.u64 %0, t; }" : "=r"(a) : "l"(p));
    return a;
}
__device__ __forceinline__ void cp16(uint32_t dst, const void* src) {
    asm volatile("cp.async.cg.shared.global [%0], [%1], 16;" :: "r"(dst), "l"(src));
}
__device__ __forceinline__ void ldsm4(uint32_t* r, uint32_t addr) {
    asm volatile("ldmatrix.sync.aligned.m8n8.x4.shared.b16 {%0,%1,%2,%3}, [%4];"
                 : "=r"(r[0]), "=r"(r[1]), "=r"(r[2]), "=r"(r[3]) : "r"(addr));
}
__device__ __forceinline__ void mma16816(float* d, const uint32_t* a, const uint32_t* b) {
    asm volatile("mma.sync.aligned.m16n8k16.row.col.f32.f16.f16.f32 "
                 "{%0,%1,%2,%3}, {%4,%5,%6,%7}, {%8,%9}, {%0,%1,%2,%3};"
                 : "+f"(d[0]), "+f"(d[1]), "+f"(d[2]), "+f"(d[3])
                 : "r"(a[0]), "r"(a[1]), "r"(a[2]), "r"(a[3]), "r"(b[0]), "r"(b[1]));
}

// =====================================================================
// Weight prep: out[n][k] = fp16(W[k][n])  (transpose + fp16 round)
// =====================================================================
__global__ void wprep_kernel(const float* __restrict__ W, __half* __restrict__ hi)
{
    __shared__ float t[32][33];
    int n0 = blockIdx.x * 32, k0 = blockIdx.y * 32;
    int tx = threadIdx.x, ty = threadIdx.y;
    for (int i = ty; i < 32; i += 8)
        t[i][tx] = W[(size_t)(k0 + i) * 1024 + n0 + tx];
    __syncthreads();
    for (int i = ty; i < 32; i += 8)
        hi[(size_t)(n0 + i) * 1024 + k0 + tx] = __float2half(t[tx][i]);
}

// =====================================================================
// A convert: fp16 of X (optionally scaled per (batch, d) by scaleK)
// =====================================================================
template<bool SCALE>
__global__ __launch_bounds__(256)
void asplit_kernel(const float* __restrict__ X, const float* __restrict__ scaleK,
                   __half* __restrict__ hi)
{
    size_t i = (size_t)blockIdx.x * 256 + threadIdx.x;   // float4 index
    float4 v = ((const float4*)X)[i];
    if (SCALE) {
        int d = (int)((i << 2) & 1023);
        int batch = (int)(i >> 21);                      // i/(8192*256)
        float4 sv = *(const float4*)&scaleK[batch * 1024 + d];
        v.x *= sv.x; v.y *= sv.y; v.z *= sv.z; v.w *= sv.w;
    }
    __half2 h0 = __floats2half2_rn(v.x, v.y);
    __half2 h1 = __floats2half2_rn(v.z, v.w);
    ((uint2*)hi)[i] = make_uint2(*(uint32_t*)&h0, *(uint32_t*)&h1);
}

// =====================================================================
// HMMA fp16 1-pass GEMM:  C = fp16(A) @ fp16(W) + bias (+addC)
// CTA tile 128x256, 8 warps (2M x 4N), warp tile 64x64, BK=32, 4-stage cp.async.
// SMEM/stage: A 128x80B (10240) + B 256x80B (20480) = 30720B; x4 = 122880B.
// =====================================================================
#define STAGE_BYTES 30720u
#define NSTAGE 4

__device__ __forceinline__ void issue_stage(
    int s, uint32_t smb, int brow, int bcol,
    const __half* Ab, const __half* Bb,
    int rr, int cc)
{
    const int st = s & (NSTAGE - 1);
    const int k0 = s << 5;
    uint32_t As = smb + (uint32_t)st * STAGE_BYTES;
    uint32_t Bs = As + 10240u;
    // A: 128 rows x 64B
    #pragma unroll
    for (int i = 0; i < 2; i++) {
        int r = rr + i * 64;
        cp16(As + (uint32_t)(r * 80 + cc * 2), Ab + (size_t)(brow + r) * 1024 + k0 + cc);
    }
    // B: 256 rows x 64B
    #pragma unroll
    for (int i = 0; i < 4; i++) {
        int r = rr + i * 64;
        cp16(Bs + (uint32_t)(r * 80 + cc * 2), Bb + (size_t)(bcol + r) * 1024 + k0 + cc);
    }
    asm volatile("cp.async.commit_group;" ::: "memory");
}

template<bool DUAL, bool ADD>
__global__ __launch_bounds__(256, 1)
void hmma_gemm_kernel(const __half* __restrict__ Ah, const __half* __restrict__ B,
                      const float* __restrict__ bias0, const float* __restrict__ bias1,
                      const float* __restrict__ addC,
                      float* __restrict__ C0, float* __restrict__ C1)
{
    extern __shared__ char smraw[];
    const uint32_t smb = smem_u32(smraw);
    const int tid = threadIdx.x, lane = tid & 31, wid = tid >> 5;
    const int wr = wid & 1, wc = wid >> 1;
    const int brow = blockIdx.y * 128, bcol = blockIdx.x * 256;

    float acc[4][8][4];
    #pragma unroll
    for (int mt = 0; mt < 4; mt++)
        #pragma unroll
        for (int nt = 0; nt < 8; nt++)
            #pragma unroll
            for (int j = 0; j < 4; j++) acc[mt][nt][j] = 0.f;

    const int rr = tid >> 2;         // 0..63
    const int cc = (tid & 3) * 8;    // element offset: 0,8,16,24

    issue_stage(0, smb, brow, bcol, Ah, B, rr, cc);
    issue_stage(1, smb, brow, bcol, Ah, B, rr, cc);
    issue_stage(2, smb, brow, bcol, Ah, B, rr, cc);

    const int am  = wr * 64 + (lane & 15);
    const int akh = (lane >> 4) * 8;
    const int g   = lane >> 3;
    const int bn  = wc * 64 + (lane & 7) + (g >> 1) * 8;
    const int bkh = (g & 1) * 8;

    for (int s = 0; s < 32; s++) {
        asm volatile("cp.async.wait_group 2;" ::: "memory");
        __syncthreads();
        if (s + 3 < 32) issue_stage(s + 3, smb, brow, bcol, Ah, B, rr, cc);
        else            asm volatile("cp.async.commit_group;" ::: "memory");

        uint32_t Asb = smb + (uint32_t)(s & (NSTAGE - 1)) * STAGE_BYTES;
        uint32_t Bsb = Asb + 10240u;
        #pragma unroll
        for (int kk = 0; kk < 2; kk++) {
            const int k = kk * 16;
            uint32_t a[4][4], b[4][4];
            #pragma unroll
            for (int mt = 0; mt < 4; mt++)
                ldsm4(a[mt], Asb + (uint32_t)((am + mt * 16) * 80 + (k + akh) * 2));
            #pragma unroll
            for (int bt = 0; bt < 4; bt++)
                ldsm4(b[bt], Bsb + (uint32_t)((bn + bt * 16) * 80 + (k + bkh) * 2));
            #pragma unroll
            for (int mt = 0; mt < 4; mt++)
                #pragma unroll
                for (int nt = 0; nt < 8; nt++)
                    mma16816(acc[mt][nt], a[mt], &b[nt >> 1][(nt & 1) * 2]);
        }
    }

    // ---- epilogue
    const float* bias = bias0;
    float* Cd = C0;
    int ceff = bcol;
    if (DUAL && bcol >= 1024) { bias = bias1; Cd = C1; ceff = bcol - 1024; }

    #pragma unroll
    for (int mt = 0; mt < 4; mt++) {
        const int r = brow + wr * 64 + mt * 16 + (lane >> 2);
        #pragma unroll
        for (int nt = 0; nt < 8; nt++) {
            const int c = ceff + wc * 64 + nt * 8 + (lane & 3) * 2;
            float2 bi = *(const float2*)&bias[c];
            float2 v0 = make_float2(acc[mt][nt][0] + bi.x, acc[mt][nt][1] + bi.y);
            float2 v1 = make_float2(acc[mt][nt][2] + bi.x, acc[mt][nt][3] + bi.y);
            if (ADD) {
                float2 a0 = *(const float2*)&addC[(size_t)r * 1024 + c];
                float2 a1 = *(const float2*)&addC[(size_t)(r + 8) * 1024 + c];
                v0.x += a0.x; v0.y += a0.y; v1.x += a1.x; v1.y += a1.y;
            }
            *(float2*)&Cd[(size_t)r * 1024 + c] = v0;
            *(float2*)&Cd[(size_t)(r + 8) * 1024 + c] = v1;
        }
    }
}

// =====================================================================
// score[b,h,s] = (X[b,s,:] (* mul[b,:]) . Wa[:,h] + ba[h]) * 0.125 + mask[b,s]
// 1024 threads = 32 warps = 32 rows per block (amortizes the 64KB Wa smem fill)
// =====================================================================
__global__ __launch_bounds__(1024)
void score_kernel(const float* __restrict__ X, const float* __restrict__ Wa,
                  const float* __restrict__ ba, const float* __restrict__ mask,
                  const float* __restrict__ mul, float* __restrict__ score)
{
    extern __shared__ float WaS[];  // [16][1024] transposed
    for (int idx = threadIdx.x; idx < 16 * 1024; idx += 1024) {
        int d = idx >> 4, h = idx & 15;
        WaS[h * 1024 + d] = Wa[idx];
    }
    __syncthreads();

    int warp = threadIdx.x >> 5, lane = threadIdx.x & 31;
    int m = blockIdx.x * 32 + warp;
    int b = m >> 13, s = m & 8191;
    const float* xrow = X + (size_t)m * 1024;
    const float* mrow = mul ? (mul + b * 1024) : (const float*)0;

    float acc[16];
    #pragma unroll
    for (int h = 0; h < 16; h++) acc[h] = 0.f;

    #pragma unroll
    for (int it = 0; it < 8; it++) {
        int d = it * 128 + lane * 4;
        float4 x = *(const float4*)&xrow[d];
        if (mrow) {
            float4 mu = *(const float4*)&mrow[d];
            x.x *= mu.x; x.y *= mu.y; x.z *= mu.z; x.w *= mu.w;
        }
        #pragma unroll
        for (int h = 0; h < 16; h++) {
            float4 w = *(const float4*)&WaS[h * 1024 + d];
            acc[h] += x.x * w.x + x.y * w.y + x.z * w.z + x.w * w.w;
        }
    }
    #pragma unroll
    for (int off = 16; off > 0; off >>= 1)
        #pragma unroll
        for (int h = 0; h < 16; h++)
            acc[h] += __shfl_xor_sync(0xffffffffu, acc[h], off);

    if (lane == 0) {
        float mk = mask[(b << 13) + s];
        #pragma unroll
        for (int h = 0; h < 16; h++)
            score[(size_t)(b * 16 + h) * 8192 + s] = (acc[h] + ba[h]) * 0.125f + mk;
    }
}

// =====================================================================
// Softmax pooling (no max subtraction: |score| < ~1, exp is safe)
// =====================================================================
__global__ __launch_bounds__(256)
void pool_partial_kernel(const float* __restrict__ score, const float* __restrict__ X,
                         float* __restrict__ part)
{
    int bh = blockIdx.x, ch = blockIdx.y;
    int b = bh >> 4, h = bh & 15;
    const float* sc = score + ((size_t)bh << 13) + (ch << 10);
    int tid = threadIdx.x;
    float acc[64];
    #pragma unroll
    for (int j = 0; j < 64; j++) acc[j] = 0.f;
    float sumw = 0.f;
    for (int s = tid; s < 1024; s += 256) {
        float w = expf(sc[s]);
        sumw += w;
        const float4* xr = (const float4*)(X + ((size_t)((b << 13) + (ch << 10) + s)) * 1024 + h * 64);
        #pragma unroll
        for (int j = 0; j < 16; j++) {
            float4 v = xr[j];
            acc[4*j+0] += w*v.x; acc[4*j+1] += w*v.y;
            acc[4*j+2] += w*v.z; acc[4*j+3] += w*v.w;
        }
    }
    #pragma unroll
    for (int off = 16; off > 0; off >>= 1) {
        sumw += __shfl_xor_sync(0xffffffffu, sumw, off);
        #pragma unroll
        for (int j = 0; j < 64; j++)
            acc[j] += __shfl_xor_sync(0xffffffffu, acc[j], off);
    }
    __shared__ float sacc[8][64];
    __shared__ float ssum[8];
    int warp = tid >> 5, lane = tid & 31;
    if (lane == 0) ssum[warp] = sumw;
    #pragma unroll
    for (int j = 0; j < 64; j++)
        if ((j & 31) == lane) sacc[warp][j] = acc[j];
    __syncthreads();
    if (tid < 64) {
        float tot = 0.f, Z = 0.f;
        #pragma unroll
        for (int w = 0; w < 8; w++) { tot += sacc[w][tid]; Z += ssum[w]; }
        float* p = part + (size_t)(bh * 8 + ch) * 65;
        p[tid] = tot;
        if (tid == 0) p[64] = Z;
    }
}

__global__ void pool_combine_kernel(const float* __restrict__ part, const float* __restrict__ mul,
                                    float* __restrict__ pooled)
{
    int bh = blockIdx.x, tid = threadIdx.x;  // block 64
    int b = bh >> 4, h = bh & 15;
    float tot = 0.f, Z = 0.f;
    #pragma unroll
    for (int ch = 0; ch < 8; ch++) {
        const float* p = part + (size_t)(bh * 8 + ch) * 65;
        tot += p[tid]; Z += p[64];
    }
    float r = tot / Z;
    if (mul) r *= mul[b * 1024 + h * 64 + tid];
    pooled[b * 1024 + h * 64 + tid] = r;
}

// =====================================================================
extern "C" void kernel_launch(void* const* d_in, const int* in_sizes, int n_in,
                              void* d_out, int out_size)
{
    const float* hs   = (const float*)d_in[0];
    const float* mask = (const float*)d_in[1];
    const float* Wq   = (const float*)d_in[2];
    const float* bq   = (const float*)d_in[3];
    const float* Wqa  = (const float*)d_in[4];
    const float* bqa  = (const float*)d_in[5];
    const float* Wk   = (const float*)d_in[6];
    const float* bk   = (const float*)d_in[7];
    const float* Wka  = (const float*)d_in[8];
    const float* bka  = (const float*)d_in[9];
    const float* Wt   = (const float*)d_in[10];
    const float* bt   = (const float*)d_in[11];
    float* out = (float*)d_out;

    float *mq, *mk, *sco, *part, *pq, *pk;
    __half *Ah, *bqk, *btp;
    cudaGetSymbolAddress((void**)&mq, g_mq);
    cudaGetSymbolAddress((void**)&mk, g_mk);
    cudaGetSymbolAddress((void**)&sco, g_score);
    cudaGetSymbolAddress((void**)&part, g_part);
    cudaGetSymbolAddress((void**)&pq, g_pq);
    cudaGetSymbolAddress((void**)&pk, g_pk);
    cudaGetSymbolAddress((void**)&Ah, g_Ah);
    cudaGetSymbolAddress((void**)&bqk, g_Bqk);
    cudaGetSymbolAddress((void**)&btp, g_Bt);

    const int GSMEM = 122880;
    cudaFuncSetAttribute(hmma_gemm_kernel<true,  false>,
                         cudaFuncAttributeMaxDynamicSharedMemorySize, GSMEM);
    cudaFuncSetAttribute(hmma_gemm_kernel<false, true>,
                         cudaFuncAttributeMaxDynamicSharedMemorySize, GSMEM);
    cudaFuncSetAttribute(score_kernel, cudaFuncAttributeMaxDynamicSharedMemorySize, 65536);

    // ---- weight prep: transpose + fp16 round
    dim3 wblk(32, 8), wgrd(32, 32);
    wprep_kernel<<<wgrd, wblk>>>(Wq, bqk);
    wprep_kernel<<<wgrd, wblk>>>(Wk, bqk + 1024 * 1024);
    wprep_kernel<<<wgrd, wblk>>>(Wt, btp);

    // ---- convert hs to fp16
    asplit_kernel<false><<<32768, 256>>>(hs, nullptr, Ah);

    // ---- fused mixed_q / mixed_k GEMM (N=2048 over [Wq|Wk]), 1-pass fp16
    hmma_gemm_kernel<true, false><<<dim3(8, 256), 256, GSMEM>>>(
        Ah, bqk, bq, bk, nullptr, mq, mk);

    // ---- q attention pooling
    score_kernel<<<1024, 1024, 65536>>>(mq, Wqa, bqa, mask, nullptr, sco);
    pool_partial_kernel<<<dim3(64, 8), 256>>>(sco, mq, part);
    pool_combine_kernel<<<64, 64>>>(part, nullptr, pq);

    // ---- k attention pooling (mixed_qk = mixed_k * pooled_q, never materialized)
    score_kernel<<<1024, 1024, 65536>>>(mk, Wka, bka, mask, pq, sco);
    pool_partial_kernel<<<dim3(64, 8), 256>>>(sco, mk, part);
    pool_combine_kernel<<<64, 64>>>(part, pq, pk);

    // ---- convert (mixed_q * pooled_k) to fp16
    asplit_kernel<true><<<32768, 256>>>(mq, pk, Ah);

    // ---- out = (mixed_q * pooled_k) @ Wt + bt + mixed_q, 1-pass fp16
    hmma_gemm_kernel<false, true><<<dim3(4, 256), 256, GSMEM>>>(
        Ah, btp, bt, nullptr, mq, out, nullptr);
}

// round 15
// speedup vs baseline: 7.3504x; 1.1067x over previous
#include <cuda_runtime.h>
#include <cuda_fp16.h>
#include <math.h>
#include <stdint.h>

#define B_  4
#define S_  8192
#define D_  1024
#define H_  16
#define M_  (B_*S_)

// ---------------- scratch (device globals; no cudaMalloc) ----------------
__device__ __half g_Ah[(size_t)M_ * D_];                // fp16(hs)
__device__ __half g_mqh[(size_t)M_ * D_];               // fp16 mixed_q
__device__ __half g_mkh[(size_t)M_ * D_];               // fp16 mixed_k
__device__ __half g_Bqk[2048 * 1024];                   // [n,k] fp16 (Wq cols | Wk cols)
__device__ float  g_Wtt[1024 * 1024];                   // Wt^T fp32 [n,k]
__device__ __half g_Bt4[4 * 1024 * 1024];               // per-batch fp16(Wt^T * pk)
__device__ float g_score[B_ * H_ * S_];
__device__ float g_part[512 * 65];
__device__ float g_pq[B_ * D_];
__device__ float g_pk[B_ * D_];

// ---------------- helpers (sm_80-era PTX only: portable to sm_103) ----------------
__device__ __forceinline__ uint32_t smem_u32(const void* p) {
    uint32_t a;
    asm("{ .reg .u64 t; cvta.to.shared.u64 t, %1; cvt.u32.u64 %0, t; }" : "=r"(a) : "l"(p));
    return a;
}
__device__ __forceinline__ void cp16(uint32_t dst, const void* src) {
    asm volatile("cp.async.cg.shared.global [%0], [%1], 16;" :: "r"(dst), "l"(src));
}
__device__ __forceinline__ void ldsm4(uint32_t* r, uint32_t addr) {
    asm volatile("ldmatrix.sync.aligned.m8n8.x4.shared.b16 {%0,%1,%2,%3}, [%4];"
                 : "=r"(r[0]), "=r"(r[1]), "=r"(r[2]), "=r"(r[3]) : "r"(addr));
}
__device__ __forceinline__ void mma16816(float* d, const uint32_t* a, const uint32_t* b) {
    asm volatile("mma.sync.aligned.m16n8k16.row.col.f32.f16.f16.f32 "
                 "{%0,%1,%2,%3}, {%4,%5,%6,%7}, {%8,%9}, {%0,%1,%2,%3};"
                 : "+f"(d[0]), "+f"(d[1]), "+f"(d[2]), "+f"(d[3])
                 : "r"(a[0]), "r"(a[1]), "r"(a[2]), "r"(a[3]), "r"(b[0]), "r"(b[1]));
}

// =====================================================================
// Weight prep
// =====================================================================
__global__ void wprep16_kernel(const float* __restrict__ W, __half* __restrict__ o)
{
    __shared__ float t[32][33];
    int n0 = blockIdx.x * 32, k0 = blockIdx.y * 32;
    int tx = threadIdx.x, ty = threadIdx.y;
    for (int i = ty; i < 32; i += 8)
        t[i][tx] = W[(size_t)(k0 + i) * 1024 + n0 + tx];
    __syncthreads();
    for (int i = ty; i < 32; i += 8)
        o[(size_t)(n0 + i) * 1024 + k0 + tx] = __float2half(t[tx][i]);
}
__global__ void wprep32_kernel(const float* __restrict__ W, float* __restrict__ o)
{
    __shared__ float t[32][33];
    int n0 = blockIdx.x * 32, k0 = blockIdx.y * 32;
    int tx = threadIdx.x, ty = threadIdx.y;
    for (int i = ty; i < 32; i += 8)
        t[i][tx] = W[(size_t)(k0 + i) * 1024 + n0 + tx];
    __syncthreads();
    for (int i = ty; i < 32; i += 8)
        o[(size_t)(n0 + i) * 1024 + k0 + tx] = t[tx][i];
}

// B4[b][n][k] = fp16(Wtt[n][k] * pk[b][k])   (single rounding of the product)
__global__ __launch_bounds__(256)
void wtscale_kernel(const float* __restrict__ Wtt, const float* __restrict__ pk,
                    __half* __restrict__ B4)
{
    int i = blockIdx.x * 256 + threadIdx.x;   // float4 index into [n][k]
    int k4 = (i << 2) & 1023;
    float4 w = ((const float4*)Wtt)[i];
    #pragma unroll
    for (int b = 0; b < 4; b++) {
        float4 s = *(const float4*)&pk[b * 1024 + k4];
        __half2 h0 = __floats2half2_rn(w.x * s.x, w.y * s.y);
        __half2 h1 = __floats2half2_rn(w.z * s.z, w.w * s.w);
        ((uint2*)(B4 + ((size_t)b << 20)))[i] =
            make_uint2(*(uint32_t*)&h0, *(uint32_t*)&h1);
    }
}

// =====================================================================
// A convert: fp16 of hs
// =====================================================================
__global__ __launch_bounds__(256)
void asplit_kernel(const float* __restrict__ X, __half* __restrict__ hi)
{
    size_t i = (size_t)blockIdx.x * 256 + threadIdx.x;   // float4 index
    float4 v = ((const float4*)X)[i];
    __half2 h0 = __floats2half2_rn(v.x, v.y);
    __half2 h1 = __floats2half2_rn(v.z, v.w);
    ((uint2*)hi)[i] = make_uint2(*(uint32_t*)&h0, *(uint32_t*)&h1);
}

// =====================================================================
// HMMA fp16 1-pass GEMM. CTA 128x256, 8 warps, warp tile 64x64, BK=32,
// 4-stage cp.async.  G3=false: dual fp16 outputs (mq|mk) + fp32 bias.
// G3=true: per-batch B (Bt4), fp32 output, fp16 residual addC.
// =====================================================================
#define STAGE_BYTES 30720u
#define NSTAGE 4

__device__ __forceinline__ void issue_stage(
    int s, uint32_t smb, int brow, int bcol,
    const __half* Ab, const __half* Bb, int rr, int cc)
{
    const int st = s & (NSTAGE - 1);
    const int k0 = s << 5;
    uint32_t As = smb + (uint32_t)st * STAGE_BYTES;
    uint32_t Bs = As + 10240u;
    #pragma unroll
    for (int i = 0; i < 2; i++) {
        int r = rr + i * 64;
        cp16(As + (uint32_t)(r * 80 + cc * 2), Ab + (size_t)(brow + r) * 1024 + k0 + cc);
    }
    #pragma unroll
    for (int i = 0; i < 4; i++) {
        int r = rr + i * 64;
        cp16(Bs + (uint32_t)(r * 80 + cc * 2), Bb + (size_t)(bcol + r) * 1024 + k0 + cc);
    }
    asm volatile("cp.async.commit_group;" ::: "memory");
}

template<bool G3>
__global__ __launch_bounds__(256, 1)
void hmma_gemm_kernel(const __half* __restrict__ Ah, const __half* __restrict__ B,
                      const float* __restrict__ bias0, const float* __restrict__ bias1,
                      const __half* __restrict__ addCh,
                      void* __restrict__ C0v, void* __restrict__ C1v)
{
    extern __shared__ char smraw[];
    const uint32_t smb = smem_u32(smraw);
    const int tid = threadIdx.x, lane = tid & 31, wid = tid >> 5;
    const int wr = wid & 1, wc = wid >> 1;
    const int brow = blockIdx.y * 128, bcol = blockIdx.x * 256;

    const __half* Bb = B;
    if (G3) Bb += ((size_t)(brow >> 13)) << 20;   // per-batch scaled Wt

    float acc[4][8][4];
    #pragma unroll
    for (int mt = 0; mt < 4; mt++)
        #pragma unroll
        for (int nt = 0; nt < 8; nt++)
            #pragma unroll
            for (int j = 0; j < 4; j++) acc[mt][nt][j] = 0.f;

    const int rr = tid >> 2;
    const int cc = (tid & 3) * 8;

    issue_stage(0, smb, brow, bcol, Ah, Bb, rr, cc);
    issue_stage(1, smb, brow, bcol, Ah, Bb, rr, cc);
    issue_stage(2, smb, brow, bcol, Ah, Bb, rr, cc);

    const int am  = wr * 64 + (lane & 15);
    const int akh = (lane >> 4) * 8;
    const int g   = lane >> 3;
    const int bn  = wc * 64 + (lane & 7) + (g >> 1) * 8;
    const int bkh = (g & 1) * 8;

    for (int s = 0; s < 32; s++) {
        asm volatile("cp.async.wait_group 2;" ::: "memory");
        __syncthreads();
        if (s + 3 < 32) issue_stage(s + 3, smb, brow, bcol, Ah, Bb, rr, cc);
        else            asm volatile("cp.async.commit_group;" ::: "memory");

        uint32_t Asb = smb + (uint32_t)(s & (NSTAGE - 1)) * STAGE_BYTES;
        uint32_t Bsb = Asb + 10240u;
        #pragma unroll
        for (int kk = 0; kk < 2; kk++) {
            const int k = kk * 16;
            uint32_t a[4][4], b[4][4];
            #pragma unroll
            for (int mt = 0; mt < 4; mt++)
                ldsm4(a[mt], Asb + (uint32_t)((am + mt * 16) * 80 + (k + akh) * 2));
            #pragma unroll
            for (int bt = 0; bt < 4; bt++)
                ldsm4(b[bt], Bsb + (uint32_t)((bn + bt * 16) * 80 + (k + bkh) * 2));
            #pragma unroll
            for (int mt = 0; mt < 4; mt++)
                #pragma unroll
                for (int nt = 0; nt < 8; nt++)
                    mma16816(acc[mt][nt], a[mt], &b[nt >> 1][(nt & 1) * 2]);
        }
    }

    if (!G3) {
        // ---- fp16 dual-output epilogue (mixed_q | mixed_k), bias added
        const float* bias = bias0;
        __half* Cd = (__half*)C0v;
        int ceff = bcol;
        if (bcol >= 1024) { bias = bias1; Cd = (__half*)C1v; ceff = bcol - 1024; }
        #pragma unroll
        for (int mt = 0; mt < 4; mt++) {
            const int r = brow + wr * 64 + mt * 16 + (lane >> 2);
            #pragma unroll
            for (int nt = 0; nt < 8; nt++) {
                const int c = ceff + wc * 64 + nt * 8 + (lane & 3) * 2;
                float2 bi = *(const float2*)&bias[c];
                __half2 h0 = __floats2half2_rn(acc[mt][nt][0] + bi.x, acc[mt][nt][1] + bi.y);
                __half2 h1 = __floats2half2_rn(acc[mt][nt][2] + bi.x, acc[mt][nt][3] + bi.y);
                *(uint32_t*)&Cd[(size_t)r * 1024 + c] = *(uint32_t*)&h0;
                *(uint32_t*)&Cd[(size_t)(r + 8) * 1024 + c] = *(uint32_t*)&h1;
            }
        }
    } else {
        // ---- fp32 output epilogue with fp16 residual
        float* Cd = (float*)C0v;
        #pragma unroll
        for (int mt = 0; mt < 4; mt++) {
            const int r = brow + wr * 64 + mt * 16 + (lane >> 2);
            #pragma unroll
            for (int nt = 0; nt < 8; nt++) {
                const int c = bcol + wc * 64 + nt * 8 + (lane & 3) * 2;
                float2 bi = *(const float2*)&bias0[c];
                uint32_t a0u = *(const uint32_t*)&addCh[(size_t)r * 1024 + c];
                uint32_t a1u = *(const uint32_t*)&addCh[(size_t)(r + 8) * 1024 + c];
                float2 a0 = __half22float2(*(__half2*)&a0u);
                float2 a1 = __half22float2(*(__half2*)&a1u);
                float2 v0 = make_float2(acc[mt][nt][0] + bi.x + a0.x,
                                        acc[mt][nt][1] + bi.y + a0.y);
                float2 v1 = make_float2(acc[mt][nt][2] + bi.x + a1.x,
                                        acc[mt][nt][3] + bi.y + a1.y);
                *(float2*)&Cd[(size_t)r * 1024 + c] = v0;
                *(float2*)&Cd[(size_t)(r + 8) * 1024 + c] = v1;
            }
        }
    }
}

// =====================================================================
// score[b,h,s] = (X[b,s,:] (* mul[b,:]) . Wa[:,h] + ba[h]) * 0.125 + mask
// X fp16, Wa cached in smem as fp16.  1024 thr = 32 rows/block.
// =====================================================================
__global__ __launch_bounds__(1024)
void score_kernel(const __half* __restrict__ X, const float* __restrict__ Wa,
                  const float* __restrict__ ba, const float* __restrict__ mask,
                  const float* __restrict__ mul, float* __restrict__ score)
{
    extern __shared__ __half WaS[];  // [16][1024] transposed, fp16
    for (int idx = threadIdx.x; idx < 16 * 1024; idx += 1024) {
        int d = idx >> 4, h = idx & 15;
        WaS[h * 1024 + d] = __float2half(Wa[idx]);
    }
    __syncthreads();

    int warp = threadIdx.x >> 5, lane = threadIdx.x & 31;
    int m = blockIdx.x * 32 + warp;
    int b = m >> 13, s = m & 8191;
    const __half* xrow = X + (size_t)m * 1024;
    const float* mrow = mul ? (mul + b * 1024) : (const float*)0;

    float acc[16];
    #pragma unroll
    for (int h = 0; h < 16; h++) acc[h] = 0.f;

    #pragma unroll
    for (int it = 0; it < 8; it++) {
        int d = it * 128 + lane * 4;
        uint2 xu = *(const uint2*)&xrow[d];        // 4 halves
        float2 x01 = __half22float2(*(__half2*)&xu.x);
        float2 x23 = __half22float2(*(__half2*)&xu.y);
        if (mrow) {
            float4 mu = *(const float4*)&mrow[d];
            x01.x *= mu.x; x01.y *= mu.y; x23.x *= mu.z; x23.y *= mu.w;
        }
        #pragma unroll
        for (int h = 0; h < 16; h++) {
            uint2 wu = *(const uint2*)&WaS[h * 1024 + d];
            float2 w01 = __half22float2(*(__half2*)&wu.x);
            float2 w23 = __half22float2(*(__half2*)&wu.y);
            acc[h] += x01.x * w01.x + x01.y * w01.y + x23.x * w23.x + x23.y * w23.y;
        }
    }
    #pragma unroll
    for (int off = 16; off > 0; off >>= 1)
        #pragma unroll
        for (int h = 0; h < 16; h++)
            acc[h] += __shfl_xor_sync(0xffffffffu, acc[h], off);

    if (lane == 0) {
        float mk = mask[(b << 13) + s];
        #pragma unroll
        for (int h = 0; h < 16; h++)
            score[(size_t)(b * 16 + h) * 8192 + s] = (acc[h] + ba[h]) * 0.125f + mk;
    }
}

// =====================================================================
// Softmax pooling (no max subtraction: |score| < ~1, exp safe). X fp16.
// =====================================================================
__global__ __launch_bounds__(256)
void pool_partial_kernel(const float* __restrict__ score, const __half* __restrict__ X,
                         float* __restrict__ part)
{
    int bh = blockIdx.x, ch = blockIdx.y;
    int b = bh >> 4, h = bh & 15;
    const float* sc = score + ((size_t)bh << 13) + (ch << 10);
    int tid = threadIdx.x;
    float acc[64];
    #pragma unroll
    for (int j = 0; j < 64; j++) acc[j] = 0.f;
    float sumw = 0.f;
    for (int s = tid; s < 1024; s += 256) {
        float w = expf(sc[s]);
        sumw += w;
        const uint4* xr = (const uint4*)(X + ((size_t)((b << 13) + (ch << 10) + s)) * 1024 + h * 64);
        #pragma unroll
        for (int j = 0; j < 8; j++) {
            uint4 u = xr[j];
            float2 f0 = __half22float2(*(__half2*)&u.x);
            float2 f1 = __half22float2(*(__half2*)&u.y);
            float2 f2 = __half22float2(*(__half2*)&u.z);
            float2 f3 = __half22float2(*(__half2*)&u.w);
            acc[8*j+0] += w*f0.x; acc[8*j+1] += w*f0.y;
            acc[8*j+2] += w*f1.x; acc[8*j+3] += w*f1.y;
            acc[8*j+4] += w*f2.x; acc[8*j+5] += w*f2.y;
            acc[8*j+6] += w*f3.x; acc[8*j+7] += w*f3.y;
        }
    }
    #pragma unroll
    for (int off = 16; off > 0; off >>= 1) {
        sumw += __shfl_xor_sync(0xffffffffu, sumw, off);
        #pragma unroll
        for (int j = 0; j < 64; j++)
            acc[j] += __shfl_xor_sync(0xffffffffu, acc[j], off);
    }
    __shared__ float sacc[8][64];
    __shared__ float ssum[8];
    int warp = tid >> 5, lane = tid & 31;
    if (lane == 0) ssum[warp] = sumw;
    #pragma unroll
    for (int j = 0; j < 64; j++)
        if ((j & 31) == lane) sacc[warp][j] = acc[j];
    __syncthreads();
    if (tid < 64) {
        float tot = 0.f, Z = 0.f;
        #pragma unroll
        for (int w = 0; w < 8; w++) { tot += sacc[w][tid]; Z += ssum[w]; }
        float* p = part + (size_t)(bh * 8 + ch) * 65;
        p[tid] = tot;
        if (tid == 0) p[64] = Z;
    }
}

__global__ void pool_combine_kernel(const float* __restrict__ part, const float* __restrict__ mul,
                                    float* __restrict__ pooled)
{
    int bh = blockIdx.x, tid = threadIdx.x;  // block 64
    int b = bh >> 4, h = bh & 15;
    float tot = 0.f, Z = 0.f;
    #pragma unroll
    for (int ch = 0; ch < 8; ch++) {
        const float* p = part + (size_t)(bh * 8 + ch) * 65;
        tot += p[tid]; Z += p[64];
    }
    float r = tot / Z;
    if (mul) r *= mul[b * 1024 + h * 64 + tid];
    pooled[b * 1024 + h * 64 + tid] = r;
}

// =====================================================================
extern "C" void kernel_launch(void* const* d_in, const int* in_sizes, int n_in,
                              void* d_out, int out_size)
{
    const float* hs   = (const float*)d_in[0];
    const float* mask = (const float*)d_in[1];
    const float* Wq   = (const float*)d_in[2];
    const float* bq   = (const float*)d_in[3];
    const float* Wqa  = (const float*)d_in[4];
    const float* bqa  = (const float*)d_in[5];
    const float* Wk   = (const float*)d_in[6];
    const float* bk   = (const float*)d_in[7];
    const float* Wka  = (const float*)d_in[8];
    const float* bka  = (const float*)d_in[9];
    const float* Wt   = (const float*)d_in[10];
    const float* bt   = (const float*)d_in[11];
    float* out = (float*)d_out;

    float *sco, *part, *pq, *pk, *wtt;
    __half *Ah, *mqh, *mkh, *bqk, *bt4;
    cudaGetSymbolAddress((void**)&Ah,  g_Ah);
    cudaGetSymbolAddress((void**)&mqh, g_mqh);
    cudaGetSymbolAddress((void**)&mkh, g_mkh);
    cudaGetSymbolAddress((void**)&bqk, g_Bqk);
    cudaGetSymbolAddress((void**)&wtt, g_Wtt);
    cudaGetSymbolAddress((void**)&bt4, g_Bt4);
    cudaGetSymbolAddress((void**)&sco, g_score);
    cudaGetSymbolAddress((void**)&part, g_part);
    cudaGetSymbolAddress((void**)&pq, g_pq);
    cudaGetSymbolAddress((void**)&pk, g_pk);

    const int GSMEM = 122880;
    cudaFuncSetAttribute(hmma_gemm_kernel<false>,
                         cudaFuncAttributeMaxDynamicSharedMemorySize, GSMEM);
    cudaFuncSetAttribute(hmma_gemm_kernel<true>,
                         cudaFuncAttributeMaxDynamicSharedMemorySize, GSMEM);

    // ---- weight prep
    dim3 wblk(32, 8), wgrd(32, 32);
    wprep16_kernel<<<wgrd, wblk>>>(Wq, bqk);
    wprep16_kernel<<<wgrd, wblk>>>(Wk, bqk + 1024 * 1024);
    wprep32_kernel<<<wgrd, wblk>>>(Wt, wtt);

    // ---- convert hs to fp16
    asplit_kernel<<<32768, 256>>>(hs, Ah);

    // ---- fused mixed_q / mixed_k GEMM (N=2048), fp16 outputs w/ bias
    hmma_gemm_kernel<false><<<dim3(8, 256), 256, GSMEM>>>(
        Ah, bqk, bq, bk, nullptr, mqh, mkh);

    // ---- q attention pooling
    score_kernel<<<1024, 1024, 32768>>>(mqh, Wqa, bqa, mask, nullptr, sco);
    pool_partial_kernel<<<dim3(64, 8), 256>>>(sco, mqh, part);
    pool_combine_kernel<<<64, 64>>>(part, nullptr, pq);

    // ---- k attention pooling (mixed_qk = mixed_k * pooled_q, never materialized)
    score_kernel<<<1024, 1024, 32768>>>(mkh, Wka, bka, mask, pq, sco);
    pool_partial_kernel<<<dim3(64, 8), 256>>>(sco, mkh, part);
    pool_combine_kernel<<<64, 64>>>(part, pq, pk);

    // ---- fold pooled_k into Wt: Bt4[b] = fp16(Wt^T * pk[b])
    wtscale_kernel<<<1024, 256>>>(wtt, pk, bt4);

    // ---- out = mixed_q @ Bt4[batch] + bt + mixed_q  (A column-scale folded into B)
    hmma_gemm_kernel<true><<<dim3(4, 256), 256, GSMEM>>>(
        mqh, bt4, bt, nullptr, mqh, out, nullptr);
}